// round 14
// baseline (speedup 1.0000x reference)
#include <cuda_runtime.h>
#include <cstdint>
#include <math.h>

#define N_TOK 2048
#define BATCH 2
#define DIM   1024
#define HEADS 16
#define DHEAD 64
#define ROWS  (BATCH * N_TOK)   // 4096
#define K2DIM 512               // DIM/2 bf16x2 pairs per row

// ---------------- device scratch (allocation-free per harness rules) --------
__device__ float g_q[ROWS * DIM];
__device__ float g_kv[ROWS * 2 * DHEAD];
__device__ float g_k[ROWS * DHEAD];
__device__ float g_v[ROWS * DHEAD];
__device__ float g_knull[DHEAD];
__device__ float g_vnull[DHEAD];
__device__ float g_h0[N_TOK * DIM];          // fp32 (feeds w2_kernel)
__device__ float g_t1[N_TOK * DIM];
__device__ float g_btab[HEADS * N_TOK];
__device__ float g_y[ROWS * DIM];
// packed bf16 hi/lo operand arrays [row][K/2]
__device__ uint32_t g_xnh[ROWS * K2DIM],   g_xnl[ROWS * K2DIM];
__device__ uint32_t g_h0h[N_TOK * K2DIM],  g_h0l[N_TOK * K2DIM];
__device__ uint32_t g_aoh[ROWS * K2DIM],   g_aol[ROWS * K2DIM];
__device__ uint32_t g_WqTh[DIM * K2DIM],   g_WqTl[DIM * K2DIM];
__device__ uint32_t g_WkvTh[2 * DHEAD * K2DIM], g_WkvTl[2 * DHEAD * K2DIM];
__device__ uint32_t g_w1Th[DIM * K2DIM],   g_w1Tl[DIM * K2DIM];
__device__ uint32_t g_WoutTh[DIM * K2DIM], g_WoutTl[DIM * K2DIM];

// ================= packed f32x2 helpers (Blackwell, base sm_100) ============
#define FFMA2(acc, a, b) \
    asm("fma.rn.f32x2 %0, %1, %2, %0;" : "+l"(acc) : "l"(a), "l"(b))
static __device__ __forceinline__ float hadd2(unsigned long long v) {
    uint32_t lo, hi;
    asm("mov.b64 {%0,%1}, %2;" : "=r"(lo), "=r"(hi) : "l"(v));
    return __uint_as_float(lo) + __uint_as_float(hi);
}

// ================= bf16 split-2 helpers =====================================
static __device__ __forceinline__ void split2_bf(float x0, float x1,
                                                 uint32_t& hi, uint32_t& lo) {
    uint32_t h;
    asm("cvt.rn.bf16x2.f32 %0, %1, %2;" : "=r"(h) : "f"(x1), "f"(x0));
    float h0 = __uint_as_float(h << 16);
    float h1 = __uint_as_float(h & 0xffff0000u);
    float r0 = x0 - h0;
    float r1 = x1 - h1;
    asm("cvt.rn.bf16x2.f32 %0, %1, %2;" : "=r"(lo) : "f"(r1), "f"(r0));
    hi = h;
}
static __device__ __forceinline__ void mma_bf16(float* c, const uint32_t* a,
                                                const uint32_t* b) {
    asm volatile(
        "mma.sync.aligned.m16n8k16.row.col.f32.bf16.bf16.f32 "
        "{%0,%1,%2,%3}, {%4,%5,%6,%7}, {%8,%9}, {%0,%1,%2,%3};"
        : "+f"(c[0]), "+f"(c[1]), "+f"(c[2]), "+f"(c[3])
        : "r"(a[0]), "r"(a[1]), "r"(a[2]), "r"(a[3]), "r"(b[0]), "r"(b[1]));
}

// ================= cp.async helpers (sm_80+) ================================
static __device__ __forceinline__ uint32_t smem_u32(const void* p) {
    uint32_t a;
    asm("{ .reg .u64 t; cvta.to.shared.u64 t, %1; cvt.u32.u64 %0, t; }" : "=r"(a) : "l"(p));
    return a;
}
#define CP16(dst, src)  asm volatile("cp.async.cg.shared.global [%0], [%1], 16;" :: "r"(dst), "l"(src) : "memory")
#define CP_COMMIT()     asm volatile("cp.async.commit_group;" ::: "memory")
#define CP_WAIT1()      asm volatile("cp.async.wait_group 1;" ::: "memory")

// ================= fat bf16-split2 GEMM (multi-job), 3-stage, occ 2 =========
// Per-block job decode: each job is a 128x128-tiled GEMM C=A@Bt^T with packed
// bf16 hi/lo operands [row][K2DIM]. Jobs laid out consecutively in blockIdx.x.
struct GJob {
    const uint32_t *Ah, *Al, *Bh, *Bl;
    float* C;
    int N, nbx, blk0;
};

#define GROW 12                    // uint32 per smem row (8 pairs + 4 pad)
#define STAGE_U32 6144             // 4 arrays x 128*GROW
#define GEMM_SMEM_BYTES (3 * STAGE_U32 * 4)   // 73728

__global__ __launch_bounds__(256, 2) void gemm_fat(GJob j0, GJob j1, GJob j2) {
    extern __shared__ uint32_t sh[];
    const int bx = blockIdx.x;
    const GJob jb = (bx >= j2.blk0) ? j2 : (bx >= j1.blk0) ? j1 : j0;
    const int rel = bx - jb.blk0;
    const int m0 = (rel / jb.nbx) * 128, n0 = (rel % jb.nbx) * 128;
    const int N = jb.N;

    const int tid = threadIdx.x, wid = tid >> 5, lane = tid & 31;
    const int g = lane >> 2, tig = lane & 3;
    const int wm = wid & 3, wn = wid >> 2;
    const int lrow = tid >> 1, half = tid & 1;
    const uint32_t* gA_h = jb.Ah + (size_t)(m0 + lrow) * K2DIM + half * 4;
    const uint32_t* gA_l = jb.Al + (size_t)(m0 + lrow) * K2DIM + half * 4;
    const uint32_t* gB_h = jb.Bh + (size_t)(n0 + lrow) * K2DIM + half * 4;
    const uint32_t* gB_l = jb.Bl + (size_t)(n0 + lrow) * K2DIM + half * 4;
    const uint32_t sbase = smem_u32(sh);
    const uint32_t drow = (uint32_t)lrow * (GROW * 4) + half * 16;

    const int nt = K2DIM >> 3;   // k-tiles of 16 elems = 8 pairs

#define ISSUE(kt, s) do { \
        uint32_t d = sbase + (uint32_t)(s) * (STAGE_U32 * 4) + drow; \
        int ko = (kt) * 8; \
        CP16(d,          gA_h + ko); \
        CP16(d + 6144,   gA_l + ko); \
        CP16(d + 12288,  gB_h + ko); \
        CP16(d + 18432,  gB_l + ko); \
        CP_COMMIT(); } while (0)

    ISSUE(0, 0);
    ISSUE(1, 1);
    float acc[2][8][4] = {};
    int stage = 0;
    for (int kt = 0; kt < nt; kt++) {
        CP_WAIT1();
        __syncthreads();
        if (kt + 2 < nt) {
            int s2 = stage + 2; if (s2 >= 3) s2 -= 3;
            ISSUE(kt + 2, s2);
        } else {
            CP_COMMIT();   // keep wait_group counting uniform
        }
        const uint32_t* SAh = sh + stage * STAGE_U32;
        const uint32_t* SAl = SAh + 1536;
        const uint32_t* SBh = SAh + 3072;
        const uint32_t* SBl = SAh + 4608;
        uint32_t a_h[2][4], a_l[2][4];
        #pragma unroll
        for (int tm = 0; tm < 2; tm++) {
            const int rb = (wm * 32 + tm * 16 + g) * GROW + tig;
            a_h[tm][0] = SAh[rb];               a_h[tm][1] = SAh[rb + 8 * GROW];
            a_h[tm][2] = SAh[rb + 4];           a_h[tm][3] = SAh[rb + 8 * GROW + 4];
            a_l[tm][0] = SAl[rb];               a_l[tm][1] = SAl[rb + 8 * GROW];
            a_l[tm][2] = SAl[rb + 4];           a_l[tm][3] = SAl[rb + 8 * GROW + 4];
        }
        #pragma unroll
        for (int tn = 0; tn < 8; tn++) {
            const int rb = (wn * 64 + tn * 8 + g) * GROW + tig;
            uint32_t b_h[2] = { SBh[rb], SBh[rb + 4] };
            uint32_t b_l[2] = { SBl[rb], SBl[rb + 4] };
            #pragma unroll
            for (int tm = 0; tm < 2; tm++) {
                mma_bf16(acc[tm][tn], a_h[tm], b_h);
                mma_bf16(acc[tm][tn], a_l[tm], b_h);
                mma_bf16(acc[tm][tn], a_h[tm], b_l);
            }
        }
        stage++; if (stage >= 3) stage -= 3;
    }
#undef ISSUE
    #pragma unroll
    for (int tm = 0; tm < 2; tm++)
        #pragma unroll
        for (int tn = 0; tn < 8; tn++) {
            const int row = m0 + wm * 32 + tm * 16 + g;
            const int col = n0 + wn * 64 + tn * 8 + 2 * tig;
            *(float2*)&jb.C[(size_t)row * N + col]       = make_float2(acc[tm][tn][0], acc[tm][tn][1]);
            *(float2*)&jb.C[(size_t)(row + 8) * N + col] = make_float2(acc[tm][tn][2], acc[tm][tn][3]);
        }
}

// ---------------- fat transpose + split (4 weight matrices, one launch) -----
struct TJob { const float* B; uint32_t* Th; uint32_t* Tl; int Nd, nbx, blk0; };

__global__ void transpose_split4(TJob t0, TJob t1, TJob t2, TJob t3) {
    __shared__ float t[32][33];
    const int bx = blockIdx.x;
    const TJob jb = (bx >= t3.blk0) ? t3 : (bx >= t2.blk0) ? t2 : (bx >= t1.blk0) ? t1 : t0;
    const int rel = bx - jb.blk0;
    const int n0 = (rel % jb.nbx) * 32, k0 = (rel / jb.nbx) * 32;
    const int tid = threadIdx.x;
    {
        const int lr = tid >> 3, lc = (tid & 7) * 4;
        float4 v = *(const float4*)(jb.B + (size_t)(k0 + lr) * jb.Nd + n0 + lc);
        t[lr][lc] = v.x; t[lr][lc + 1] = v.y; t[lr][lc + 2] = v.z; t[lr][lc + 3] = v.w;
    }
    __syncthreads();
    const int p = tid & 15, nl0 = tid >> 4;
    #pragma unroll
    for (int u = 0; u < 2; u++) {
        const int n = nl0 + u * 16;
        uint32_t h, l;
        split2_bf(t[2 * p][n], t[2 * p + 1][n], h, l);
        jb.Th[(size_t)(n0 + n) * K2DIM + (k0 >> 1) + p] = h;
        jb.Tl[(size_t)(n0 + n) * K2DIM + (k0 >> 1) + p] = l;
    }
}

// ---------------- block reduce ----------------------------------------------
static __device__ __forceinline__ float blockReduceSum(float v, float* sh) {
    #pragma unroll
    for (int o = 16; o; o >>= 1) v += __shfl_xor_sync(0xffffffffu, v, o);
    int w = threadIdx.x >> 5;
    if ((threadIdx.x & 31) == 0) sh[w] = v;
    __syncthreads();
    if (threadIdx.x < 32) {
        v = (threadIdx.x < 8) ? sh[threadIdx.x] : 0.f;
        #pragma unroll
        for (int o = 4; o; o >>= 1) v += __shfl_xor_sync(0xffffffffu, v, o);
        if (threadIdx.x == 0) sh[0] = v;
    }
    __syncthreads();
    float r = sh[0];
    __syncthreads();
    return r;
}

// ---------------- fused prep: ln_split (rows<4096) + mlp0_split -------------
__global__ void prep_fused(const float* __restrict__ x, const float* __restrict__ gn,
                           const float* __restrict__ w0, const float* __restrict__ b0,
                           const float* __restrict__ g0) {
    __shared__ float sh[32];
    const int tid = threadIdx.x;
    if (blockIdx.x < ROWS) {
        const int row = blockIdx.x;
        float4 v = *(const float4*)(x + (size_t)row * DIM + tid * 4);
        float s = v.x + v.y + v.z + v.w;
        s = blockReduceSum(s, sh);
        float mean = s * (1.f / DIM);
        float d0 = v.x - mean, d1 = v.y - mean, d2 = v.z - mean, d3 = v.w - mean;
        float qv = d0 * d0 + d1 * d1 + d2 * d2 + d3 * d3;
        qv = blockReduceSum(qv, sh);
        float rstd = rsqrtf(qv * (1.f / DIM) + 1e-5f);
        float4 gg = *(const float4*)(gn + tid * 4);
        float o0 = d0 * rstd * gg.x, o1 = d1 * rstd * gg.y;
        float o2 = d2 * rstd * gg.z, o3 = d3 * rstd * gg.w;
        uint32_t h0, l0, h1, l1;
        split2_bf(o0, o1, h0, l0);
        split2_bf(o2, o3, h1, l1);
        ((uint2*)g_xnh)[(size_t)row * 256 + tid] = make_uint2(h0, h1);
        ((uint2*)g_xnl)[(size_t)row * 256 + tid] = make_uint2(l0, l1);
    } else {
        const int d = blockIdx.x - ROWS;
        const float pos = (float)d;
        const int c = tid * 4;
        float4 w4 = *(const float4*)(w0 + c);
        float4 b4 = *(const float4*)(b0 + c);
        float v0 = pos * w4.x + b4.x, v1 = pos * w4.y + b4.y;
        float v2 = pos * w4.z + b4.z, v3 = pos * w4.w + b4.w;
        float s = v0 + v1 + v2 + v3;
        s = blockReduceSum(s, sh);
        float mean = s * (1.f / DIM);
        float d0 = v0 - mean, d1 = v1 - mean, d2 = v2 - mean, d3 = v3 - mean;
        float qv = d0 * d0 + d1 * d1 + d2 * d2 + d3 * d3;
        qv = blockReduceSum(qv, sh);
        float rstd = rsqrtf(qv * (1.f / DIM) + 1e-5f);
        float4 g4 = *(const float4*)(g0 + c);
        float o0 = d0 * rstd * g4.x; o0 = o0 / (1.f + __expf(-o0));
        float o1 = d1 * rstd * g4.y; o1 = o1 / (1.f + __expf(-o1));
        float o2 = d2 * rstd * g4.z; o2 = o2 / (1.f + __expf(-o2));
        float o3 = d3 * rstd * g4.w; o3 = o3 / (1.f + __expf(-o3));
        uint32_t h0, l0, h1, l1;
        split2_bf(o0, o1, h0, l0);
        split2_bf(o2, o3, h1, l1);
        ((uint2*)g_h0h)[(size_t)d * 256 + tid] = make_uint2(h0, h1);
        ((uint2*)g_h0l)[(size_t)d * 256 + tid] = make_uint2(l0, l1);
    }
}

// ---------------- layernorm rows (fp32 out; optional bias + silu) -----------
__global__ void ln_rows(const float* __restrict__ in, const float* __restrict__ bias,
                        const float* __restrict__ g, float* __restrict__ out, int dosilu) {
    __shared__ float sh[32];
    const int row = blockIdx.x, tid = threadIdx.x;
    float v[4];
    #pragma unroll
    for (int u = 0; u < 4; u++) {
        int c = tid + u * 256;
        v[u] = in[(size_t)row * DIM + c] + (bias ? bias[c] : 0.f);
    }
    float s = v[0] + v[1] + v[2] + v[3];
    s = blockReduceSum(s, sh);
    float mean = s * (1.f / DIM);
    float qv = 0.f;
    #pragma unroll
    for (int u = 0; u < 4; u++) { float d = v[u] - mean; qv += d * d; }
    qv = blockReduceSum(qv, sh);
    float rstd = rsqrtf(qv * (1.f / DIM) + 1e-5f);
    #pragma unroll
    for (int u = 0; u < 4; u++) {
        int c = tid + u * 256;
        float o = (v[u] - mean) * rstd * g[c];
        if (dosilu) o = o / (1.f + __expf(-o));
        out[(size_t)row * DIM + c] = o;
    }
}

// ---------------- btabT[16][2048] = h1 @ w2 + b2 ----------------------------
__global__ void w2_kernel(const float* __restrict__ w2, const float* __restrict__ b2) {
    __shared__ float sh[DIM];
    const int d = blockIdx.x, tid = threadIdx.x;
    #pragma unroll
    for (int u = 0; u < 4; u++) sh[tid + u * 256] = g_h0[(size_t)d * DIM + tid + u * 256];
    __syncthreads();
    const int gi = tid >> 4, l16 = tid & 15;
    float s = 0.f;
    for (int kk = l16; kk < DIM; kk += 16) s += sh[kk] * w2[kk * HEADS + gi];
    #pragma unroll
    for (int o = 8; o; o >>= 1) s += __shfl_xor_sync(0xffffffffu, s, o);
    if (l16 == 0) g_btab[gi * N_TOK + d] = s + b2[gi];
}

// ---------------- fused norms: qnorm + kvnorm + nullprep --------------------
#define QN_BLOCKS (ROWS * HEADS / 8)   // 8192
#define KV_BLOCKS (ROWS / 8)           // 512

__global__ void norm_fused(const float* __restrict__ qs, const float* __restrict__ ks,
                           const float* __restrict__ nkv) {
    const int bx = blockIdx.x, tid = threadIdx.x;
    const int lane = tid & 31;
    if (bx < QN_BLOCKS) {
        const int gw = (bx * 256 + tid) >> 5;
        const int row = gw >> 4, h = gw & 15;
        float* p = g_q + (size_t)row * DIM + h * DHEAD;
        const int d0 = lane * 2;
        float a = p[d0], b = p[d0 + 1];
        float ss = a * a + b * b;
        #pragma unroll
        for (int o = 16; o; o >>= 1) ss += __shfl_xor_sync(0xffffffffu, ss, o);
        float inv = 1.f / fmaxf(sqrtf(ss), 1e-12f);
        p[d0]     = a * inv * qs[d0];
        p[d0 + 1] = b * inv * qs[d0 + 1];
    } else if (bx < QN_BLOCKS + KV_BLOCKS) {
        const int row = ((bx - QN_BLOCKS) * 256 + tid) >> 5;
        const float* kvp = g_kv + (size_t)row * 128;
        const int d0 = lane * 2;
        float a = kvp[d0], b = kvp[d0 + 1];
        float ss = a * a + b * b;
        #pragma unroll
        for (int o = 16; o; o >>= 1) ss += __shfl_xor_sync(0xffffffffu, ss, o);
        float inv = 1.f / fmaxf(sqrtf(ss), 1e-12f);
        g_k[(size_t)row * DHEAD + d0]     = a * inv * ks[d0];
        g_k[(size_t)row * DHEAD + d0 + 1] = b * inv * ks[d0 + 1];
        g_v[(size_t)row * DHEAD + d0]     = kvp[64 + d0];
        g_v[(size_t)row * DHEAD + d0 + 1] = kvp[64 + d0 + 1];
    } else if (tid < 32) {
        const int d0 = lane * 2;
        float a = nkv[d0], b = nkv[d0 + 1];
        float ss = a * a + b * b;
        #pragma unroll
        for (int o = 16; o; o >>= 1) ss += __shfl_xor_sync(0xffffffffu, ss, o);
        float inv = 1.f / fmaxf(sqrtf(ss), 1e-12f);
        g_knull[d0]     = a * inv * ks[d0];
        g_knull[d0 + 1] = b * inv * ks[d0 + 1];
        g_vnull[d0]     = nkv[64 + d0];
        g_vnull[d0 + 1] = nkv[64 + d0 + 1];
    }
}

// ---------------- causal MQA flash attention (128x64 tile, occ 2) -----------
// Epilogue writes split bf16 hi/lo (g_aoh/g_aol) directly via lane-pair shfl.
#define SATT 66
#define ATT_SMEM_FLOATS (128 * SATT + 64 * SATT + 64 * SATT + 128 * SATT + 192 + 64 + 64)
#define ATT_SMEM_BYTES  (ATT_SMEM_FLOATS * 4)

__global__ __launch_bounds__(256, 2) void attn_kernel(
        const float* __restrict__ q, const float* __restrict__ kbuf,
        const float* __restrict__ vbuf, const float* __restrict__ knull,
        const float* __restrict__ vnull, const float* __restrict__ nab,
        const float* __restrict__ btab) {
    extern __shared__ float sm[];
    float* Qs  = sm;
    float* Ks  = Qs + 128 * SATT;
    float* VsT = Ks + 64 * SATT;
    float* Ps  = VsT + 64 * SATT;
    float* bsl = Ps + 128 * SATT;
    float* kns = bsl + 192;
    float* vns = kns + 64;

    const int tid = threadIdx.x;
    const int tx = tid & 15, tyg = tid >> 4;
    const int r0 = tyg * 8;
    const int i0 = (gridDim.x - 1 - blockIdx.x) * 128;
    const int h  = blockIdx.y;
    const int b  = blockIdx.z;

    {
        const int row = tid >> 1, seg = (tid & 1) * 32;
        const float* src = q + (size_t)(b * N_TOK + i0 + row) * DIM + h * DHEAD + seg;
        #pragma unroll
        for (int u = 0; u < 32; u += 4) {
            float4 t4 = *(const float4*)(src + u);
            float* dst = Qs + row * SATT + seg + u;
            *(float2*)(dst)     = make_float2(t4.x, t4.y);
            *(float2*)(dst + 2) = make_float2(t4.z, t4.w);
        }
    }
    if (tid < 64) { kns[tid] = knull[tid]; vns[tid] = vnull[tid]; }
    __syncthreads();

    float m[8], l[8], o[8][4];
    {
        const float nb = nab[h];
        #pragma unroll
        for (int i = 0; i < 8; i++) {
            float p = 0.f;
            #pragma unroll
            for (int jp = 0; jp < 4; jp++) {
                const int c = tx + 16 * jp;
                p += Qs[(r0 + i) * SATT + c] * kns[c];
            }
            #pragma unroll
            for (int off = 8; off; off >>= 1)
                p += __shfl_xor_sync(0xffffffffu, p, off);
            m[i] = p * 8.f + nb;
            l[i] = 1.f;
            #pragma unroll
            for (int jp = 0; jp < 4; jp++) o[i][jp] = vns[tx + 16 * jp];
        }
    }

    const int ntiles = i0 / 64 + 2;
    for (int jt = 0; jt < ntiles; jt++) {
        const int j0 = jt * 64;
        {
            const int row = tid & 63, seg = (tid >> 6) * 16;
            const float* ksrc = kbuf + (size_t)(b * N_TOK + j0 + row) * DHEAD + seg;
            const float* vsrc = vbuf + (size_t)(b * N_TOK + j0 + row) * DHEAD + seg;
            #pragma unroll
            for (int u = 0; u < 16; u += 4) {
                float4 t4 = *(const float4*)(ksrc + u);
                float* d1 = Ks + row * SATT + seg + u;
                *(float2*)(d1)     = make_float2(t4.x, t4.y);
                *(float2*)(d1 + 2) = make_float2(t4.z, t4.w);
                float4 t5 = *(const float4*)(vsrc + u);
                VsT[(seg + u + 0) * SATT + row] = t5.x;
                VsT[(seg + u + 1) * SATT + row] = t5.y;
                VsT[(seg + u + 2) * SATT + row] = t5.z;
                VsT[(seg + u + 3) * SATT + row] = t5.w;
            }
        }
        if (tid < 191) {
            int dg = i0 - j0 + tid - 63;
            bsl[tid] = (dg >= 0 && dg < N_TOK) ? btab[h * N_TOK + dg] : 0.f;
        }
        __syncthreads();

        unsigned long long acc2[8][4] = {};
        #pragma unroll 4
        for (int dd = 0; dd < 64; dd += 2) {
            unsigned long long aq2[8], bk2[4];
            #pragma unroll
            for (int i = 0; i < 8; i++)
                aq2[i] = *(const unsigned long long*)(Qs + (r0 + i) * SATT + dd);
            #pragma unroll
            for (int jp = 0; jp < 4; jp++)
                bk2[jp] = *(const unsigned long long*)(Ks + (tx + 16 * jp) * SATT + dd);
            #pragma unroll
            for (int i = 0; i < 8; i++)
                #pragma unroll
                for (int jp = 0; jp < 4; jp++)
                    FFMA2(acc2[i][jp], aq2[i], bk2[jp]);
        }
        float s_[8][4];
        const bool needmask = (j0 >= i0);
        #pragma unroll
        for (int i = 0; i < 8; i++)
            #pragma unroll
            for (int jp = 0; jp < 4; jp++) {
                const int col = tx + 16 * jp;
                float sv = hadd2(acc2[i][jp]) * 8.f + bsl[(r0 + i) - col + 63];
                if (needmask && (j0 + col) > (i0 + r0 + i)) sv = -1e30f;
                s_[i][jp] = sv;
            }

        float fac[8];
        #pragma unroll
        for (int i = 0; i < 8; i++) {
            float mt = fmaxf(fmaxf(s_[i][0], s_[i][1]), fmaxf(s_[i][2], s_[i][3]));
            #pragma unroll
            for (int off = 8; off; off >>= 1)
                mt = fmaxf(mt, __shfl_xor_sync(0xffffffffu, mt, off));
            float nm = fmaxf(m[i], mt);
            fac[i] = __expf(m[i] - nm);
            m[i] = nm;
            float lt = 0.f;
            #pragma unroll
            for (int jp = 0; jp < 4; jp++) {
                float p = __expf(s_[i][jp] - nm);
                s_[i][jp] = p;
                lt += p;
            }
            #pragma unroll
            for (int off = 8; off; off >>= 1)
                lt += __shfl_xor_sync(0xffffffffu, lt, off);
            l[i] = l[i] * fac[i] + lt;
        }
        #pragma unroll
        for (int i = 0; i < 8; i++)
            #pragma unroll
            for (int jp = 0; jp < 4; jp++)
                Ps[(r0 + i) * SATT + tx + 16 * jp] = s_[i][jp];
        __syncthreads();

        // reuse acc2 as PV accumulator (register pressure for occ 2)
        #pragma unroll
        for (int i = 0; i < 8; i++)
            #pragma unroll
            for (int jp = 0; jp < 4; jp++)
                acc2[i][jp] = 0ULL;
        #pragma unroll 4
        for (int jj = 0; jj < 64; jj += 2) {
            unsigned long long pa2[8], vb2[4];
            #pragma unroll
            for (int i = 0; i < 8; i++)
                pa2[i] = *(const unsigned long long*)(Ps + (r0 + i) * SATT + jj);
            #pragma unroll
            for (int jp = 0; jp < 4; jp++)
                vb2[jp] = *(const unsigned long long*)(VsT + (tx + 16 * jp) * SATT + jj);
            #pragma unroll
            for (int i = 0; i < 8; i++)
                #pragma unroll
                for (int jp = 0; jp < 4; jp++)
                    FFMA2(acc2[i][jp], pa2[i], vb2[jp]);
        }
        #pragma unroll
        for (int i = 0; i < 8; i++)
            #pragma unroll
            for (int jp = 0; jp < 4; jp++)
                o[i][jp] = o[i][jp] * fac[i] + hadd2(acc2[i][jp]);
        __syncthreads();
    }

    // epilogue: normalize + pair via shfl + split to bf16 hi/lo
    #pragma unroll
    for (int i = 0; i < 8; i++) {
        float inv = 1.f / l[i];
        const size_t rowb = (size_t)(b * N_TOK + i0 + r0 + i) * K2DIM;
        #pragma unroll
        for (int jp = 0; jp < 4; jp++) {
            float v0 = o[i][jp] * inv;
            float v1 = __shfl_xor_sync(0xffffffffu, v0, 1);
            if ((tx & 1) == 0) {
                uint32_t hi2, lo2;
                split2_bf(v0, v1, hi2, lo2);
                const int pidx = (h * DHEAD + tx + 16 * jp) >> 1;
                g_aoh[rowb + pidx] = hi2;
                g_aol[rowb + pidx] = lo2;
            }
        }
    }
}

// ---------------- launch -----------------------------------------------------
extern "C" void kernel_launch(void* const* d_in, const int* in_sizes, int n_in,
                              void* d_out, int out_size) {
    const float* x       = (const float*)d_in[0];
    const float* gn      = (const float*)d_in[2];
    const float* Wq      = (const float*)d_in[3];
    const float* Wkv     = (const float*)d_in[4];
    const float* q_scale = (const float*)d_in[5];
    const float* k_scale = (const float*)d_in[6];
    const float* null_kv = (const float*)d_in[7];
    const float* nab     = (const float*)d_in[8];
    const float* w0      = (const float*)d_in[9];
    const float* b0      = (const float*)d_in[10];
    const float* g0      = (const float*)d_in[11];
    const float* w1      = (const float*)d_in[12];
    const float* b1      = (const float*)d_in[13];
    const float* g1      = (const float*)d_in[14];
    const float* w2      = (const float*)d_in[15];
    const float* b2      = (const float*)d_in[16];
    const float* Wout    = (const float*)d_in[17];
    const float* gout    = (const float*)d_in[18];
    float* out = (float*)d_out;

    float *pq, *pkv, *pk, *pv, *pknull, *pvnull, *ph0, *pt1, *pbtab, *py;
    uint32_t *pxnh, *pxnl, *ph0h, *ph0l, *paoh, *paol;
    uint32_t *pWqTh, *pWqTl, *pWkvTh, *pWkvTl, *pw1Th, *pw1Tl, *pWoutTh, *pWoutTl;
    cudaGetSymbolAddress((void**)&pq,      g_q);
    cudaGetSymbolAddress((void**)&pkv,     g_kv);
    cudaGetSymbolAddress((void**)&pk,      g_k);
    cudaGetSymbolAddress((void**)&pv,      g_v);
    cudaGetSymbolAddress((void**)&pknull,  g_knull);
    cudaGetSymbolAddress((void**)&pvnull,  g_vnull);
    cudaGetSymbolAddress((void**)&ph0,     g_h0);
    cudaGetSymbolAddress((void**)&pt1,     g_t1);
    cudaGetSymbolAddress((void**)&pbtab,   g_btab);
    cudaGetSymbolAddress((void**)&py,      g_y);
    cudaGetSymbolAddress((void**)&pxnh,    g_xnh);
    cudaGetSymbolAddress((void**)&pxnl,    g_xnl);
    cudaGetSymbolAddress((void**)&ph0h,    g_h0h);
    cudaGetSymbolAddress((void**)&ph0l,    g_h0l);
    cudaGetSymbolAddress((void**)&paoh,    g_aoh);
    cudaGetSymbolAddress((void**)&paol,    g_aol);
    cudaGetSymbolAddress((void**)&pWqTh,   g_WqTh);
    cudaGetSymbolAddress((void**)&pWqTl,   g_WqTl);
    cudaGetSymbolAddress((void**)&pWkvTh,  g_WkvTh);
    cudaGetSymbolAddress((void**)&pWkvTl,  g_WkvTl);
    cudaGetSymbolAddress((void**)&pw1Th,   g_w1Th);
    cudaGetSymbolAddress((void**)&pw1Tl,   g_w1Tl);
    cudaGetSymbolAddress((void**)&pWoutTh, g_WoutTh);
    cudaGetSymbolAddress((void**)&pWoutTl, g_WoutTl);

    cudaFuncSetAttribute(attn_kernel, cudaFuncAttributeMaxDynamicSharedMemorySize, ATT_SMEM_BYTES);
    cudaFuncSetAttribute(gemm_fat, cudaFuncAttributeMaxDynamicSharedMemorySize, GEMM_SMEM_BYTES);

    // 0. transpose + split all 4 weight matrices (one fat launch)
    {
        TJob t0 = { Wq,   pWqTh,   pWqTl,   DIM, 32, 0 };
        TJob t1j = { Wkv,  pWkvTh,  pWkvTl,  2 * DHEAD, 4, 1024 };
        TJob t2 = { w1,   pw1Th,   pw1Tl,   DIM, 32, 1152 };
        TJob t3 = { Wout, pWoutTh, pWoutTl, DIM, 32, 2176 };
        transpose_split4<<<3200, 256>>>(t0, t1j, t2, t3);
    }
    // 1. fused ln_split(x) + mlp0_split
    prep_fused<<<ROWS + N_TOK, 256>>>(x, gn, w0, b0, g0);
    // 2. fat GEMM: q = xn@Wq | t1 = h0@w1 | kv = xn@Wkv (one launch, 416 blocks)
    {
        GJob j0 = { pxnh, pxnl, pWqTh,  pWqTl,  pq,  DIM, 8, 0 };
        GJob j1 = { ph0h, ph0l, pw1Th,  pw1Tl,  pt1, DIM, 8, 256 };
        GJob j2 = { pxnh, pxnl, pWkvTh, pWkvTl, pkv, 2 * DHEAD, 1, 384 };
        gemm_fat<<<416, 256, GEMM_SMEM_BYTES>>>(j0, j1, j2);
    }
    // 3. fused qnorm + kvnorm + nullprep
    norm_fused<<<QN_BLOCKS + KV_BLOCKS + 1, 256>>>(q_scale, k_scale, null_kv);
    // 4. rel-pos bias: ln(t1)+silu -> h0 ; btab = h0@w2
    ln_rows<<<N_TOK, 256>>>(pt1, b1, g1, ph0, 1);
    w2_kernel<<<N_TOK, 256>>>(w2, b2);
    // 5. flash attention (occ 2); epilogue writes split bf16 aout
    attn_kernel<<<dim3(N_TOK / 128, HEADS, BATCH), 256, ATT_SMEM_BYTES>>>(
        pq, pk, pv, pknull, pvnull, nab, pbtab);
    // 6. y = aout @ Wout ; out = ln(y) * g_out
    {
        GJob j0 = { paoh, paol, pWoutTh, pWoutTl, py, DIM, 8, 0 };
        GJob jx = { paoh, paol, pWoutTh, pWoutTl, py, DIM, 8, 1 << 30 };
        gemm_fat<<<256, 256, GEMM_SMEM_BYTES>>>(j0, jx, jx);
    }
    ln_rows<<<ROWS, 256>>>(py, nullptr, gout, out, 0);
}

// round 15
// speedup vs baseline: 1.1565x; 1.1565x over previous
#include <cuda_runtime.h>
#include <cstdint>
#include <math.h>

#define N_TOK 2048
#define BATCH 2
#define DIM   1024
#define HEADS 16
#define DHEAD 64
#define ROWS  (BATCH * N_TOK)   // 4096
#define K2DIM 512               // DIM/2 bf16x2 pairs per row

// ---------------- device scratch (allocation-free per harness rules) --------
__device__ float g_q[ROWS * DIM];
__device__ float g_kv[ROWS * 2 * DHEAD];
__device__ float g_k[ROWS * DHEAD];
__device__ float g_v[ROWS * DHEAD];
__device__ float g_knull[DHEAD];
__device__ float g_vnull[DHEAD];
__device__ float g_h0[N_TOK * DIM];          // fp32 (feeds w2_kernel)
__device__ float g_t1[N_TOK * DIM];
__device__ float g_btab[HEADS * N_TOK];
__device__ float g_y[ROWS * DIM];
// packed bf16 hi/lo operand arrays [row][K/2]
__device__ uint32_t g_xnh[ROWS * K2DIM],   g_xnl[ROWS * K2DIM];
__device__ uint32_t g_h0h[N_TOK * K2DIM],  g_h0l[N_TOK * K2DIM];
__device__ uint32_t g_aoh[ROWS * K2DIM],   g_aol[ROWS * K2DIM];
__device__ uint32_t g_WqTh[DIM * K2DIM],   g_WqTl[DIM * K2DIM];
__device__ uint32_t g_WkvTh[2 * DHEAD * K2DIM], g_WkvTl[2 * DHEAD * K2DIM];
__device__ uint32_t g_w1Th[DIM * K2DIM],   g_w1Tl[DIM * K2DIM];
__device__ uint32_t g_WoutTh[DIM * K2DIM], g_WoutTl[DIM * K2DIM];

// ================= packed f32x2 helpers (Blackwell, base sm_100) ============
#define FFMA2(acc, a, b) \
    asm("fma.rn.f32x2 %0, %1, %2, %0;" : "+l"(acc) : "l"(a), "l"(b))
static __device__ __forceinline__ float hadd2(unsigned long long v) {
    uint32_t lo, hi;
    asm("mov.b64 {%0,%1}, %2;" : "=r"(lo), "=r"(hi) : "l"(v));
    return __uint_as_float(lo) + __uint_as_float(hi);
}

// ================= bf16 split-2 helpers =====================================
static __device__ __forceinline__ void split2_bf(float x0, float x1,
                                                 uint32_t& hi, uint32_t& lo) {
    uint32_t h;
    asm("cvt.rn.bf16x2.f32 %0, %1, %2;" : "=r"(h) : "f"(x1), "f"(x0));
    float h0 = __uint_as_float(h << 16);
    float h1 = __uint_as_float(h & 0xffff0000u);
    float r0 = x0 - h0;
    float r1 = x1 - h1;
    asm("cvt.rn.bf16x2.f32 %0, %1, %2;" : "=r"(lo) : "f"(r1), "f"(r0));
    hi = h;
}
static __device__ __forceinline__ void mma_bf16(float* c, const uint32_t* a,
                                                const uint32_t* b) {
    asm volatile(
        "mma.sync.aligned.m16n8k16.row.col.f32.bf16.bf16.f32 "
        "{%0,%1,%2,%3}, {%4,%5,%6,%7}, {%8,%9}, {%0,%1,%2,%3};"
        : "+f"(c[0]), "+f"(c[1]), "+f"(c[2]), "+f"(c[3])
        : "r"(a[0]), "r"(a[1]), "r"(a[2]), "r"(a[3]), "r"(b[0]), "r"(b[1]));
}

// ================= cp.async helpers (sm_80+) ================================
static __device__ __forceinline__ uint32_t smem_u32(const void* p) {
    uint32_t a;
    asm("{ .reg .u64 t; cvta.to.shared.u64 t, %1; cvt.u32.u64 %0, t; }" : "=r"(a) : "l"(p));
    return a;
}
#define CP16(dst, src)  asm volatile("cp.async.cg.shared.global [%0], [%1], 16;" :: "r"(dst), "l"(src) : "memory")
#define CP_COMMIT()     asm volatile("cp.async.commit_group;" ::: "memory")
#define CP_WAIT1()      asm volatile("cp.async.wait_group 1;" ::: "memory")

// ================= fat bf16-split2 GEMM (multi-job), 3-stage, occ 2 =========
struct GJob {
    const uint32_t *Ah, *Al, *Bh, *Bl;
    float* C;
    int N, nbx, blk0;
};

#define GROW 12                    // uint32 per smem row (8 pairs + 4 pad)
#define STAGE_U32 6144             // 4 arrays x 128*GROW
#define GEMM_SMEM_BYTES (3 * STAGE_U32 * 4)   // 73728

__global__ __launch_bounds__(256, 2) void gemm_fat(GJob j0, GJob j1, GJob j2) {
    extern __shared__ uint32_t sh[];
    const int bx = blockIdx.x;
    const GJob jb = (bx >= j2.blk0) ? j2 : (bx >= j1.blk0) ? j1 : j0;
    const int rel = bx - jb.blk0;
    const int m0 = (rel / jb.nbx) * 128, n0 = (rel % jb.nbx) * 128;
    const int N = jb.N;

    const int tid = threadIdx.x, wid = tid >> 5, lane = tid & 31;
    const int g = lane >> 2, tig = lane & 3;
    const int wm = wid & 3, wn = wid >> 2;
    const int lrow = tid >> 1, half = tid & 1;
    const uint32_t* gA_h = jb.Ah + (size_t)(m0 + lrow) * K2DIM + half * 4;
    const uint32_t* gA_l = jb.Al + (size_t)(m0 + lrow) * K2DIM + half * 4;
    const uint32_t* gB_h = jb.Bh + (size_t)(n0 + lrow) * K2DIM + half * 4;
    const uint32_t* gB_l = jb.Bl + (size_t)(n0 + lrow) * K2DIM + half * 4;
    const uint32_t sbase = smem_u32(sh);
    const uint32_t drow = (uint32_t)lrow * (GROW * 4) + half * 16;

    const int nt = K2DIM >> 3;   // k-tiles of 16 elems = 8 pairs

#define ISSUE(kt, s) do { \
        uint32_t d = sbase + (uint32_t)(s) * (STAGE_U32 * 4) + drow; \
        int ko = (kt) * 8; \
        CP16(d,          gA_h + ko); \
        CP16(d + 6144,   gA_l + ko); \
        CP16(d + 12288,  gB_h + ko); \
        CP16(d + 18432,  gB_l + ko); \
        CP_COMMIT(); } while (0)

    ISSUE(0, 0);
    ISSUE(1, 1);
    float acc[2][8][4] = {};
    int stage = 0;
    for (int kt = 0; kt < nt; kt++) {
        CP_WAIT1();
        __syncthreads();
        if (kt + 2 < nt) {
            int s2 = stage + 2; if (s2 >= 3) s2 -= 3;
            ISSUE(kt + 2, s2);
        } else {
            CP_COMMIT();   // keep wait_group counting uniform
        }
        const uint32_t* SAh = sh + stage * STAGE_U32;
        const uint32_t* SAl = SAh + 1536;
        const uint32_t* SBh = SAh + 3072;
        const uint32_t* SBl = SAh + 4608;
        uint32_t a_h[2][4], a_l[2][4];
        #pragma unroll
        for (int tm = 0; tm < 2; tm++) {
            const int rb = (wm * 32 + tm * 16 + g) * GROW + tig;
            a_h[tm][0] = SAh[rb];               a_h[tm][1] = SAh[rb + 8 * GROW];
            a_h[tm][2] = SAh[rb + 4];           a_h[tm][3] = SAh[rb + 8 * GROW + 4];
            a_l[tm][0] = SAl[rb];               a_l[tm][1] = SAl[rb + 8 * GROW];
            a_l[tm][2] = SAl[rb + 4];           a_l[tm][3] = SAl[rb + 8 * GROW + 4];
        }
        #pragma unroll
        for (int tn = 0; tn < 8; tn++) {
            const int rb = (wn * 64 + tn * 8 + g) * GROW + tig;
            uint32_t b_h[2] = { SBh[rb], SBh[rb + 4] };
            uint32_t b_l[2] = { SBl[rb], SBl[rb + 4] };
            #pragma unroll
            for (int tm = 0; tm < 2; tm++) {
                mma_bf16(acc[tm][tn], a_h[tm], b_h);
                mma_bf16(acc[tm][tn], a_l[tm], b_h);
                mma_bf16(acc[tm][tn], a_h[tm], b_l);
            }
        }
        stage++; if (stage >= 3) stage -= 3;
    }
#undef ISSUE
    #pragma unroll
    for (int tm = 0; tm < 2; tm++)
        #pragma unroll
        for (int tn = 0; tn < 8; tn++) {
            const int row = m0 + wm * 32 + tm * 16 + g;
            const int col = n0 + wn * 64 + tn * 8 + 2 * tig;
            *(float2*)&jb.C[(size_t)row * N + col]       = make_float2(acc[tm][tn][0], acc[tm][tn][1]);
            *(float2*)&jb.C[(size_t)(row + 8) * N + col] = make_float2(acc[tm][tn][2], acc[tm][tn][3]);
        }
}

// ---------------- fat transpose + split (4 weight matrices, one launch) -----
struct TJob { const float* B; uint32_t* Th; uint32_t* Tl; int Nd, nbx, blk0; };

__global__ void transpose_split4(TJob t0, TJob t1, TJob t2, TJob t3) {
    __shared__ float t[32][33];
    const int bx = blockIdx.x;
    const TJob jb = (bx >= t3.blk0) ? t3 : (bx >= t2.blk0) ? t2 : (bx >= t1.blk0) ? t1 : t0;
    const int rel = bx - jb.blk0;
    const int n0 = (rel % jb.nbx) * 32, k0 = (rel / jb.nbx) * 32;
    const int tid = threadIdx.x;
    {
        const int lr = tid >> 3, lc = (tid & 7) * 4;
        float4 v = *(const float4*)(jb.B + (size_t)(k0 + lr) * jb.Nd + n0 + lc);
        t[lr][lc] = v.x; t[lr][lc + 1] = v.y; t[lr][lc + 2] = v.z; t[lr][lc + 3] = v.w;
    }
    __syncthreads();
    const int p = tid & 15, nl0 = tid >> 4;
    #pragma unroll
    for (int u = 0; u < 2; u++) {
        const int n = nl0 + u * 16;
        uint32_t h, l;
        split2_bf(t[2 * p][n], t[2 * p + 1][n], h, l);
        jb.Th[(size_t)(n0 + n) * K2DIM + (k0 >> 1) + p] = h;
        jb.Tl[(size_t)(n0 + n) * K2DIM + (k0 >> 1) + p] = l;
    }
}

// ---------------- block reduce ----------------------------------------------
static __device__ __forceinline__ float blockReduceSum(float v, float* sh) {
    #pragma unroll
    for (int o = 16; o; o >>= 1) v += __shfl_xor_sync(0xffffffffu, v, o);
    int w = threadIdx.x >> 5;
    if ((threadIdx.x & 31) == 0) sh[w] = v;
    __syncthreads();
    if (threadIdx.x < 32) {
        v = (threadIdx.x < 8) ? sh[threadIdx.x] : 0.f;
        #pragma unroll
        for (int o = 4; o; o >>= 1) v += __shfl_xor_sync(0xffffffffu, v, o);
        if (threadIdx.x == 0) sh[0] = v;
    }
    __syncthreads();
    float r = sh[0];
    __syncthreads();
    return r;
}

// ---------------- fused prep: ln_split (rows<4096) + mlp0_split -------------
__global__ void prep_fused(const float* __restrict__ x, const float* __restrict__ gn,
                           const float* __restrict__ w0, const float* __restrict__ b0,
                           const float* __restrict__ g0) {
    __shared__ float sh[32];
    const int tid = threadIdx.x;
    if (blockIdx.x < ROWS) {
        const int row = blockIdx.x;
        float4 v = *(const float4*)(x + (size_t)row * DIM + tid * 4);
        float s = v.x + v.y + v.z + v.w;
        s = blockReduceSum(s, sh);
        float mean = s * (1.f / DIM);
        float d0 = v.x - mean, d1 = v.y - mean, d2 = v.z - mean, d3 = v.w - mean;
        float qv = d0 * d0 + d1 * d1 + d2 * d2 + d3 * d3;
        qv = blockReduceSum(qv, sh);
        float rstd = rsqrtf(qv * (1.f / DIM) + 1e-5f);
        float4 gg = *(const float4*)(gn + tid * 4);
        float o0 = d0 * rstd * gg.x, o1 = d1 * rstd * gg.y;
        float o2 = d2 * rstd * gg.z, o3 = d3 * rstd * gg.w;
        uint32_t h0, l0, h1, l1;
        split2_bf(o0, o1, h0, l0);
        split2_bf(o2, o3, h1, l1);
        ((uint2*)g_xnh)[(size_t)row * 256 + tid] = make_uint2(h0, h1);
        ((uint2*)g_xnl)[(size_t)row * 256 + tid] = make_uint2(l0, l1);
    } else {
        const int d = blockIdx.x - ROWS;
        const float pos = (float)d;
        const int c = tid * 4;
        float4 w4 = *(const float4*)(w0 + c);
        float4 b4 = *(const float4*)(b0 + c);
        float v0 = pos * w4.x + b4.x, v1 = pos * w4.y + b4.y;
        float v2 = pos * w4.z + b4.z, v3 = pos * w4.w + b4.w;
        float s = v0 + v1 + v2 + v3;
        s = blockReduceSum(s, sh);
        float mean = s * (1.f / DIM);
        float d0 = v0 - mean, d1 = v1 - mean, d2 = v2 - mean, d3 = v3 - mean;
        float qv = d0 * d0 + d1 * d1 + d2 * d2 + d3 * d3;
        qv = blockReduceSum(qv, sh);
        float rstd = rsqrtf(qv * (1.f / DIM) + 1e-5f);
        float4 g4 = *(const float4*)(g0 + c);
        float o0 = d0 * rstd * g4.x; o0 = o0 / (1.f + __expf(-o0));
        float o1 = d1 * rstd * g4.y; o1 = o1 / (1.f + __expf(-o1));
        float o2 = d2 * rstd * g4.z; o2 = o2 / (1.f + __expf(-o2));
        float o3 = d3 * rstd * g4.w; o3 = o3 / (1.f + __expf(-o3));
        uint32_t h0, l0, h1, l1;
        split2_bf(o0, o1, h0, l0);
        split2_bf(o2, o3, h1, l1);
        ((uint2*)g_h0h)[(size_t)d * 256 + tid] = make_uint2(h0, h1);
        ((uint2*)g_h0l)[(size_t)d * 256 + tid] = make_uint2(l0, l1);
    }
}

// ---------------- layernorm rows (fp32 out; optional bias + silu) -----------
__global__ void ln_rows(const float* __restrict__ in, const float* __restrict__ bias,
                        const float* __restrict__ g, float* __restrict__ out, int dosilu) {
    __shared__ float sh[32];
    const int row = blockIdx.x, tid = threadIdx.x;
    float v[4];
    #pragma unroll
    for (int u = 0; u < 4; u++) {
        int c = tid + u * 256;
        v[u] = in[(size_t)row * DIM + c] + (bias ? bias[c] : 0.f);
    }
    float s = v[0] + v[1] + v[2] + v[3];
    s = blockReduceSum(s, sh);
    float mean = s * (1.f / DIM);
    float qv = 0.f;
    #pragma unroll
    for (int u = 0; u < 4; u++) { float d = v[u] - mean; qv += d * d; }
    qv = blockReduceSum(qv, sh);
    float rstd = rsqrtf(qv * (1.f / DIM) + 1e-5f);
    #pragma unroll
    for (int u = 0; u < 4; u++) {
        int c = tid + u * 256;
        float o = (v[u] - mean) * rstd * g[c];
        if (dosilu) o = o / (1.f + __expf(-o));
        out[(size_t)row * DIM + c] = o;
    }
}

// ---------------- btabT[16][2048] = h1 @ w2 + b2 ----------------------------
__global__ void w2_kernel(const float* __restrict__ w2, const float* __restrict__ b2) {
    __shared__ float sh[DIM];
    const int d = blockIdx.x, tid = threadIdx.x;
    #pragma unroll
    for (int u = 0; u < 4; u++) sh[tid + u * 256] = g_h0[(size_t)d * DIM + tid + u * 256];
    __syncthreads();
    const int gi = tid >> 4, l16 = tid & 15;
    float s = 0.f;
    for (int kk = l16; kk < DIM; kk += 16) s += sh[kk] * w2[kk * HEADS + gi];
    #pragma unroll
    for (int o = 8; o; o >>= 1) s += __shfl_xor_sync(0xffffffffu, s, o);
    if (l16 == 0) g_btab[gi * N_TOK + d] = s + b2[gi];
}

// ---------------- fused norms: qnorm + kvnorm + nullprep --------------------
#define QN_BLOCKS (ROWS * HEADS / 8)   // 8192
#define KV_BLOCKS (ROWS / 8)           // 512

__global__ void norm_fused(const float* __restrict__ qs, const float* __restrict__ ks,
                           const float* __restrict__ nkv) {
    const int bx = blockIdx.x, tid = threadIdx.x;
    const int lane = tid & 31;
    if (bx < QN_BLOCKS) {
        const int gw = (bx * 256 + tid) >> 5;
        const int row = gw >> 4, h = gw & 15;
        float* p = g_q + (size_t)row * DIM + h * DHEAD;
        const int d0 = lane * 2;
        float a = p[d0], b = p[d0 + 1];
        float ss = a * a + b * b;
        #pragma unroll
        for (int o = 16; o; o >>= 1) ss += __shfl_xor_sync(0xffffffffu, ss, o);
        float inv = 1.f / fmaxf(sqrtf(ss), 1e-12f);
        p[d0]     = a * inv * qs[d0];
        p[d0 + 1] = b * inv * qs[d0 + 1];
    } else if (bx < QN_BLOCKS + KV_BLOCKS) {
        const int row = ((bx - QN_BLOCKS) * 256 + tid) >> 5;
        const float* kvp = g_kv + (size_t)row * 128;
        const int d0 = lane * 2;
        float a = kvp[d0], b = kvp[d0 + 1];
        float ss = a * a + b * b;
        #pragma unroll
        for (int o = 16; o; o >>= 1) ss += __shfl_xor_sync(0xffffffffu, ss, o);
        float inv = 1.f / fmaxf(sqrtf(ss), 1e-12f);
        g_k[(size_t)row * DHEAD + d0]     = a * inv * ks[d0];
        g_k[(size_t)row * DHEAD + d0 + 1] = b * inv * ks[d0 + 1];
        g_v[(size_t)row * DHEAD + d0]     = kvp[64 + d0];
        g_v[(size_t)row * DHEAD + d0 + 1] = kvp[64 + d0 + 1];
    } else if (tid < 32) {
        const int d0 = lane * 2;
        float a = nkv[d0], b = nkv[d0 + 1];
        float ss = a * a + b * b;
        #pragma unroll
        for (int o = 16; o; o >>= 1) ss += __shfl_xor_sync(0xffffffffu, ss, o);
        float inv = 1.f / fmaxf(sqrtf(ss), 1e-12f);
        g_knull[d0]     = a * inv * ks[d0];
        g_knull[d0 + 1] = b * inv * ks[d0 + 1];
        g_vnull[d0]     = nkv[64 + d0];
        g_vnull[d0 + 1] = nkv[64 + d0 + 1];
    }
}

// ---------------- causal MQA flash attention (128x64 tile, occ 1) -----------
// Epilogue writes split bf16 hi/lo (g_aoh/g_aol) directly via lane-pair shfl.
#define SATT 66
#define ATT_SMEM_FLOATS (128 * SATT + 64 * SATT + 64 * SATT + 128 * SATT + 192 + 64 + 64)
#define ATT_SMEM_BYTES  (ATT_SMEM_FLOATS * 4)

__global__ __launch_bounds__(256, 1) void attn_kernel(
        const float* __restrict__ q, const float* __restrict__ kbuf,
        const float* __restrict__ vbuf, const float* __restrict__ knull,
        const float* __restrict__ vnull, const float* __restrict__ nab,
        const float* __restrict__ btab) {
    extern __shared__ float sm[];
    float* Qs  = sm;
    float* Ks  = Qs + 128 * SATT;
    float* VsT = Ks + 64 * SATT;
    float* Ps  = VsT + 64 * SATT;
    float* bsl = Ps + 128 * SATT;
    float* kns = bsl + 192;
    float* vns = kns + 64;

    const int tid = threadIdx.x;
    const int tx = tid & 15, tyg = tid >> 4;
    const int r0 = tyg * 8;
    const int i0 = (gridDim.x - 1 - blockIdx.x) * 128;
    const int h  = blockIdx.y;
    const int b  = blockIdx.z;

    {
        const int row = tid >> 1, seg = (tid & 1) * 32;
        const float* src = q + (size_t)(b * N_TOK + i0 + row) * DIM + h * DHEAD + seg;
        #pragma unroll
        for (int u = 0; u < 32; u += 4) {
            float4 t4 = *(const float4*)(src + u);
            float* dst = Qs + row * SATT + seg + u;
            *(float2*)(dst)     = make_float2(t4.x, t4.y);
            *(float2*)(dst + 2) = make_float2(t4.z, t4.w);
        }
    }
    if (tid < 64) { kns[tid] = knull[tid]; vns[tid] = vnull[tid]; }
    __syncthreads();

    float m[8], l[8], o[8][4];
    {
        const float nb = nab[h];
        #pragma unroll
        for (int i = 0; i < 8; i++) {
            float p = 0.f;
            #pragma unroll
            for (int jp = 0; jp < 4; jp++) {
                const int c = tx + 16 * jp;
                p += Qs[(r0 + i) * SATT + c] * kns[c];
            }
            #pragma unroll
            for (int off = 8; off; off >>= 1)
                p += __shfl_xor_sync(0xffffffffu, p, off);
            m[i] = p * 8.f + nb;
            l[i] = 1.f;
            #pragma unroll
            for (int jp = 0; jp < 4; jp++) o[i][jp] = vns[tx + 16 * jp];
        }
    }

    const int ntiles = i0 / 64 + 2;
    for (int jt = 0; jt < ntiles; jt++) {
        const int j0 = jt * 64;
        {
            const int row = tid & 63, seg = (tid >> 6) * 16;
            const float* ksrc = kbuf + (size_t)(b * N_TOK + j0 + row) * DHEAD + seg;
            const float* vsrc = vbuf + (size_t)(b * N_TOK + j0 + row) * DHEAD + seg;
            #pragma unroll
            for (int u = 0; u < 16; u += 4) {
                float4 t4 = *(const float4*)(ksrc + u);
                float* d1 = Ks + row * SATT + seg + u;
                *(float2*)(d1)     = make_float2(t4.x, t4.y);
                *(float2*)(d1 + 2) = make_float2(t4.z, t4.w);
                float4 t5 = *(const float4*)(vsrc + u);
                VsT[(seg + u + 0) * SATT + row] = t5.x;
                VsT[(seg + u + 1) * SATT + row] = t5.y;
                VsT[(seg + u + 2) * SATT + row] = t5.z;
                VsT[(seg + u + 3) * SATT + row] = t5.w;
            }
        }
        if (tid < 191) {
            int dg = i0 - j0 + tid - 63;
            bsl[tid] = (dg >= 0 && dg < N_TOK) ? btab[h * N_TOK + dg] : 0.f;
        }
        __syncthreads();

        unsigned long long acc2[8][4] = {};
        #pragma unroll 4
        for (int dd = 0; dd < 64; dd += 2) {
            unsigned long long aq2[8], bk2[4];
            #pragma unroll
            for (int i = 0; i < 8; i++)
                aq2[i] = *(const unsigned long long*)(Qs + (r0 + i) * SATT + dd);
            #pragma unroll
            for (int jp = 0; jp < 4; jp++)
                bk2[jp] = *(const unsigned long long*)(Ks + (tx + 16 * jp) * SATT + dd);
            #pragma unroll
            for (int i = 0; i < 8; i++)
                #pragma unroll
                for (int jp = 0; jp < 4; jp++)
                    FFMA2(acc2[i][jp], aq2[i], bk2[jp]);
        }
        float s_[8][4];
        const bool needmask = (j0 >= i0);
        #pragma unroll
        for (int i = 0; i < 8; i++)
            #pragma unroll
            for (int jp = 0; jp < 4; jp++) {
                const int col = tx + 16 * jp;
                float sv = hadd2(acc2[i][jp]) * 8.f + bsl[(r0 + i) - col + 63];
                if (needmask && (j0 + col) > (i0 + r0 + i)) sv = -1e30f;
                s_[i][jp] = sv;
            }

        float fac[8];
        #pragma unroll
        for (int i = 0; i < 8; i++) {
            float mt = fmaxf(fmaxf(s_[i][0], s_[i][1]), fmaxf(s_[i][2], s_[i][3]));
            #pragma unroll
            for (int off = 8; off; off >>= 1)
                mt = fmaxf(mt, __shfl_xor_sync(0xffffffffu, mt, off));
            float nm = fmaxf(m[i], mt);
            fac[i] = __expf(m[i] - nm);
            m[i] = nm;
            float lt = 0.f;
            #pragma unroll
            for (int jp = 0; jp < 4; jp++) {
                float p = __expf(s_[i][jp] - nm);
                s_[i][jp] = p;
                lt += p;
            }
            #pragma unroll
            for (int off = 8; off; off >>= 1)
                lt += __shfl_xor_sync(0xffffffffu, lt, off);
            l[i] = l[i] * fac[i] + lt;
        }
        #pragma unroll
        for (int i = 0; i < 8; i++)
            #pragma unroll
            for (int jp = 0; jp < 4; jp++)
                Ps[(r0 + i) * SATT + tx + 16 * jp] = s_[i][jp];
        __syncthreads();

        unsigned long long dacc[8][4] = {};
        #pragma unroll 4
        for (int jj = 0; jj < 64; jj += 2) {
            unsigned long long pa2[8], vb2[4];
            #pragma unroll
            for (int i = 0; i < 8; i++)
                pa2[i] = *(const unsigned long long*)(Ps + (r0 + i) * SATT + jj);
            #pragma unroll
            for (int jp = 0; jp < 4; jp++)
                vb2[jp] = *(const unsigned long long*)(VsT + (tx + 16 * jp) * SATT + jj);
            #pragma unroll
            for (int i = 0; i < 8; i++)
                #pragma unroll
                for (int jp = 0; jp < 4; jp++)
                    FFMA2(dacc[i][jp], pa2[i], vb2[jp]);
        }
        #pragma unroll
        for (int i = 0; i < 8; i++)
            #pragma unroll
            for (int jp = 0; jp < 4; jp++)
                o[i][jp] = o[i][jp] * fac[i] + hadd2(dacc[i][jp]);
        __syncthreads();
    }

    // epilogue: normalize + pair via shfl + split to bf16 hi/lo
    #pragma unroll
    for (int i = 0; i < 8; i++) {
        float inv = 1.f / l[i];
        const size_t rowb = (size_t)(b * N_TOK + i0 + r0 + i) * K2DIM;
        #pragma unroll
        for (int jp = 0; jp < 4; jp++) {
            float v0 = o[i][jp] * inv;
            float v1 = __shfl_xor_sync(0xffffffffu, v0, 1);
            if ((tx & 1) == 0) {
                uint32_t hi2, lo2;
                split2_bf(v0, v1, hi2, lo2);
                const int pidx = (h * DHEAD + tx + 16 * jp) >> 1;
                g_aoh[rowb + pidx] = hi2;
                g_aol[rowb + pidx] = lo2;
            }
        }
    }
}

// ---------------- launch -----------------------------------------------------
extern "C" void kernel_launch(void* const* d_in, const int* in_sizes, int n_in,
                              void* d_out, int out_size) {
    const float* x       = (const float*)d_in[0];
    const float* gn      = (const float*)d_in[2];
    const float* Wq      = (const float*)d_in[3];
    const float* Wkv     = (const float*)d_in[4];
    const float* q_scale = (const float*)d_in[5];
    const float* k_scale = (const float*)d_in[6];
    const float* null_kv = (const float*)d_in[7];
    const float* nab     = (const float*)d_in[8];
    const float* w0      = (const float*)d_in[9];
    const float* b0      = (const float*)d_in[10];
    const float* g0      = (const float*)d_in[11];
    const float* w1      = (const float*)d_in[12];
    const float* b1      = (const float*)d_in[13];
    const float* g1      = (const float*)d_in[14];
    const float* w2      = (const float*)d_in[15];
    const float* b2      = (const float*)d_in[16];
    const float* Wout    = (const float*)d_in[17];
    const float* gout    = (const float*)d_in[18];
    float* out = (float*)d_out;

    float *pq, *pkv, *pk, *pv, *pknull, *pvnull, *ph0, *pt1, *pbtab, *py;
    uint32_t *pxnh, *pxnl, *ph0h, *ph0l, *paoh, *paol;
    uint32_t *pWqTh, *pWqTl, *pWkvTh, *pWkvTl, *pw1Th, *pw1Tl, *pWoutTh, *pWoutTl;
    cudaGetSymbolAddress((void**)&pq,      g_q);
    cudaGetSymbolAddress((void**)&pkv,     g_kv);
    cudaGetSymbolAddress((void**)&pk,      g_k);
    cudaGetSymbolAddress((void**)&pv,      g_v);
    cudaGetSymbolAddress((void**)&pknull,  g_knull);
    cudaGetSymbolAddress((void**)&pvnull,  g_vnull);
    cudaGetSymbolAddress((void**)&ph0,     g_h0);
    cudaGetSymbolAddress((void**)&pt1,     g_t1);
    cudaGetSymbolAddress((void**)&pbtab,   g_btab);
    cudaGetSymbolAddress((void**)&py,      g_y);
    cudaGetSymbolAddress((void**)&pxnh,    g_xnh);
    cudaGetSymbolAddress((void**)&pxnl,    g_xnl);
    cudaGetSymbolAddress((void**)&ph0h,    g_h0h);
    cudaGetSymbolAddress((void**)&ph0l,    g_h0l);
    cudaGetSymbolAddress((void**)&paoh,    g_aoh);
    cudaGetSymbolAddress((void**)&paol,    g_aol);
    cudaGetSymbolAddress((void**)&pWqTh,   g_WqTh);
    cudaGetSymbolAddress((void**)&pWqTl,   g_WqTl);
    cudaGetSymbolAddress((void**)&pWkvTh,  g_WkvTh);
    cudaGetSymbolAddress((void**)&pWkvTl,  g_WkvTl);
    cudaGetSymbolAddress((void**)&pw1Th,   g_w1Th);
    cudaGetSymbolAddress((void**)&pw1Tl,   g_w1Tl);
    cudaGetSymbolAddress((void**)&pWoutTh, g_WoutTh);
    cudaGetSymbolAddress((void**)&pWoutTl, g_WoutTl);

    cudaFuncSetAttribute(attn_kernel, cudaFuncAttributeMaxDynamicSharedMemorySize, ATT_SMEM_BYTES);
    cudaFuncSetAttribute(gemm_fat, cudaFuncAttributeMaxDynamicSharedMemorySize, GEMM_SMEM_BYTES);

    // 0. transpose + split all 4 weight matrices (one fat launch)
    {
        TJob t0 = { Wq,   pWqTh,   pWqTl,   DIM, 32, 0 };
        TJob t1j = { Wkv,  pWkvTh,  pWkvTl,  2 * DHEAD, 4, 1024 };
        TJob t2 = { w1,   pw1Th,   pw1Tl,   DIM, 32, 1152 };
        TJob t3 = { Wout, pWoutTh, pWoutTl, DIM, 32, 2176 };
        transpose_split4<<<3200, 256>>>(t0, t1j, t2, t3);
    }
    // 1. fused ln_split(x) + mlp0_split
    prep_fused<<<ROWS + N_TOK, 256>>>(x, gn, w0, b0, g0);
    // 2. fat GEMM: q = xn@Wq | t1 = h0@w1 | kv = xn@Wkv (one launch, 416 blocks)
    {
        GJob j0 = { pxnh, pxnl, pWqTh,  pWqTl,  pq,  DIM, 8, 0 };
        GJob j1 = { ph0h, ph0l, pw1Th,  pw1Tl,  pt1, DIM, 8, 256 };
        GJob j2 = { pxnh, pxnl, pWkvTh, pWkvTl, pkv, 2 * DHEAD, 1, 384 };
        gemm_fat<<<416, 256, GEMM_SMEM_BYTES>>>(j0, j1, j2);
    }
    // 3. fused qnorm + kvnorm + nullprep
    norm_fused<<<QN_BLOCKS + KV_BLOCKS + 1, 256>>>(q_scale, k_scale, null_kv);
    // 4. rel-pos bias: ln(t1)+silu -> h0 ; btab = h0@w2
    ln_rows<<<N_TOK, 256>>>(pt1, b1, g1, ph0, 1);
    w2_kernel<<<N_TOK, 256>>>(w2, b2);
    // 5. flash attention (occ 1); epilogue writes split bf16 aout
    attn_kernel<<<dim3(N_TOK / 128, HEADS, BATCH), 256, ATT_SMEM_BYTES>>>(
        pq, pk, pv, pknull, pvnull, nab, pbtab);
    // 6. y = aout @ Wout ; out = ln(y) * g_out
    {
        GJob j0 = { paoh, paol, pWoutTh, pWoutTl, py, DIM, 8, 0 };
        GJob jx = { paoh, paol, pWoutTh, pWoutTl, py, DIM, 8, 1 << 30 };
        gemm_fat<<<256, 256, GEMM_SMEM_BYTES>>>(j0, jx, jx);
    }
    ln_rows<<<ROWS, 256>>>(py, nullptr, gout, out, 0);
}

// round 17
// speedup vs baseline: 1.8662x; 1.6137x over previous
#include <cuda_runtime.h>
#include <cstdint>
#include <math.h>

#define N_TOK 2048
#define BATCH 2
#define DIM   1024
#define HEADS 16
#define DHEAD 64
#define ROWS  (BATCH * N_TOK)   // 4096
#define K2DIM 512               // DIM/2 bf16x2 pairs per row

// ---------------- device scratch (allocation-free per harness rules) --------
__device__ float g_q[ROWS * DIM];
__device__ float g_kv[ROWS * 2 * DHEAD];
__device__ float g_k[ROWS * DHEAD];
__device__ float g_v[ROWS * DHEAD];
__device__ float g_knull[DHEAD];
__device__ float g_vnull[DHEAD];
__device__ float g_h0[N_TOK * DIM];          // fp32 (feeds w2_kernel)
__device__ float g_t1[N_TOK * DIM];
__device__ float g_btab[HEADS * N_TOK];
__device__ float g_y[ROWS * DIM];
// packed bf16 hi/lo operand arrays [row][K/2]
__device__ uint32_t g_xnh[ROWS * K2DIM],   g_xnl[ROWS * K2DIM];
__device__ uint32_t g_h0h[N_TOK * K2DIM],  g_h0l[N_TOK * K2DIM];
__device__ uint32_t g_aoh[ROWS * K2DIM],   g_aol[ROWS * K2DIM];
__device__ uint32_t g_WqTh[DIM * K2DIM],   g_WqTl[DIM * K2DIM];
__device__ uint32_t g_WkvTh[2 * DHEAD * K2DIM], g_WkvTl[2 * DHEAD * K2DIM];
__device__ uint32_t g_w1Th[DIM * K2DIM],   g_w1Tl[DIM * K2DIM];
__device__ uint32_t g_WoutTh[DIM * K2DIM], g_WoutTl[DIM * K2DIM];

// ================= bf16 split-2 helpers =====================================
static __device__ __forceinline__ void split2_bf(float x0, float x1,
                                                 uint32_t& hi, uint32_t& lo) {
    uint32_t h;
    asm("cvt.rn.bf16x2.f32 %0, %1, %2;" : "=r"(h) : "f"(x1), "f"(x0));
    float h0 = __uint_as_float(h << 16);
    float h1 = __uint_as_float(h & 0xffff0000u);
    float r0 = x0 - h0;
    float r1 = x1 - h1;
    asm("cvt.rn.bf16x2.f32 %0, %1, %2;" : "=r"(lo) : "f"(r1), "f"(r0));
    hi = h;
}
static __device__ __forceinline__ float bfu(uint32_t u, int hi) {
    return __uint_as_float(hi ? (u & 0xffff0000u) : (u << 16));
}
static __device__ __forceinline__ void mma_bf16(float* c, const uint32_t* a,
                                                const uint32_t* b) {
    asm volatile(
        "mma.sync.aligned.m16n8k16.row.col.f32.bf16.bf16.f32 "
        "{%0,%1,%2,%3}, {%4,%5,%6,%7}, {%8,%9}, {%0,%1,%2,%3};"
        : "+f"(c[0]), "+f"(c[1]), "+f"(c[2]), "+f"(c[3])
        : "r"(a[0]), "r"(a[1]), "r"(a[2]), "r"(a[3]), "r"(b[0]), "r"(b[1]));
}

// ================= cp.async helpers (sm_80+) ================================
static __device__ __forceinline__ uint32_t smem_u32(const void* p) {
    uint32_t a;
    asm("{ .reg .u64 t; cvta.to.shared.u64 t, %1; cvt.u32.u64 %0, t; }" : "=r"(a) : "l"(p));
    return a;
}
#define CP16(dst, src)  asm volatile("cp.async.cg.shared.global [%0], [%1], 16;" :: "r"(dst), "l"(src) : "memory")
#define CP_COMMIT()     asm volatile("cp.async.commit_group;" ::: "memory")
#define CP_WAIT1()      asm volatile("cp.async.wait_group 1;" ::: "memory")

// ================= fat bf16-split2 GEMM (multi-job), 3-stage, occ 2 =========
struct GJob {
    const uint32_t *Ah, *Al, *Bh, *Bl;
    float* C;
    int N, nbx, blk0;
};

#define GROW 12                    // uint32 per smem row (8 pairs + 4 pad)
#define STAGE_U32 6144             // 4 arrays x 128*GROW
#define GEMM_SMEM_BYTES (3 * STAGE_U32 * 4)   // 73728

__global__ __launch_bounds__(256, 2) void gemm_fat(GJob j0, GJob j1, GJob j2) {
    extern __shared__ uint32_t sh[];
    const int bx = blockIdx.x;
    const GJob jb = (bx >= j2.blk0) ? j2 : (bx >= j1.blk0) ? j1 : j0;
    const int rel = bx - jb.blk0;
    const int m0 = (rel / jb.nbx) * 128, n0 = (rel % jb.nbx) * 128;
    const int N = jb.N;

    const int tid = threadIdx.x, wid = tid >> 5, lane = tid & 31;
    const int g = lane >> 2, tig = lane & 3;
    const int wm = wid & 3, wn = wid >> 2;
    const int lrow = tid >> 1, half = tid & 1;
    const uint32_t* gA_h = jb.Ah + (size_t)(m0 + lrow) * K2DIM + half * 4;
    const uint32_t* gA_l = jb.Al + (size_t)(m0 + lrow) * K2DIM + half * 4;
    const uint32_t* gB_h = jb.Bh + (size_t)(n0 + lrow) * K2DIM + half * 4;
    const uint32_t* gB_l = jb.Bl + (size_t)(n0 + lrow) * K2DIM + half * 4;
    const uint32_t sbase = smem_u32(sh);
    const uint32_t drow = (uint32_t)lrow * (GROW * 4) + half * 16;

    const int nt = K2DIM >> 3;   // k-tiles of 16 elems = 8 pairs

#define ISSUE(kt, s) do { \
        uint32_t d = sbase + (uint32_t)(s) * (STAGE_U32 * 4) + drow; \
        int ko = (kt) * 8; \
        CP16(d,          gA_h + ko); \
        CP16(d + 6144,   gA_l + ko); \
        CP16(d + 12288,  gB_h + ko); \
        CP16(d + 18432,  gB_l + ko); \
        CP_COMMIT(); } while (0)

    ISSUE(0, 0);
    ISSUE(1, 1);
    float acc[2][8][4] = {};
    int stage = 0;
    for (int kt = 0; kt < nt; kt++) {
        CP_WAIT1();
        __syncthreads();
        if (kt + 2 < nt) {
            int s2 = stage + 2; if (s2 >= 3) s2 -= 3;
            ISSUE(kt + 2, s2);
        } else {
            CP_COMMIT();   // keep wait_group counting uniform
        }
        const uint32_t* SAh = sh + stage * STAGE_U32;
        const uint32_t* SAl = SAh + 1536;
        const uint32_t* SBh = SAh + 3072;
        const uint32_t* SBl = SAh + 4608;
        uint32_t a_h[2][4], a_l[2][4];
        #pragma unroll
        for (int tm = 0; tm < 2; tm++) {
            const int rb = (wm * 32 + tm * 16 + g) * GROW + tig;
            a_h[tm][0] = SAh[rb];               a_h[tm][1] = SAh[rb + 8 * GROW];
            a_h[tm][2] = SAh[rb + 4];           a_h[tm][3] = SAh[rb + 8 * GROW + 4];
            a_l[tm][0] = SAl[rb];               a_l[tm][1] = SAl[rb + 8 * GROW];
            a_l[tm][2] = SAl[rb + 4];           a_l[tm][3] = SAl[rb + 8 * GROW + 4];
        }
        #pragma unroll
        for (int tn = 0; tn < 8; tn++) {
            const int rb = (wn * 64 + tn * 8 + g) * GROW + tig;
            uint32_t b_h[2] = { SBh[rb], SBh[rb + 4] };
            uint32_t b_l[2] = { SBl[rb], SBl[rb + 4] };
            #pragma unroll
            for (int tm = 0; tm < 2; tm++) {
                mma_bf16(acc[tm][tn], a_h[tm], b_h);
                mma_bf16(acc[tm][tn], a_l[tm], b_h);
                mma_bf16(acc[tm][tn], a_h[tm], b_l);
            }
        }
        stage++; if (stage >= 3) stage -= 3;
    }
#undef ISSUE
    #pragma unroll
    for (int tm = 0; tm < 2; tm++)
        #pragma unroll
        for (int tn = 0; tn < 8; tn++) {
            const int row = m0 + wm * 32 + tm * 16 + g;
            const int col = n0 + wn * 64 + tn * 8 + 2 * tig;
            *(float2*)&jb.C[(size_t)row * N + col]       = make_float2(acc[tm][tn][0], acc[tm][tn][1]);
            *(float2*)&jb.C[(size_t)(row + 8) * N + col] = make_float2(acc[tm][tn][2], acc[tm][tn][3]);
        }
}

// ---------------- fat transpose + split (4 weight matrices, one launch) -----
struct TJob { const float* B; uint32_t* Th; uint32_t* Tl; int Nd, nbx, blk0; };

__global__ void transpose_split4(TJob t0, TJob t1, TJob t2, TJob t3) {
    __shared__ float t[32][33];
    const int bx = blockIdx.x;
    const TJob jb = (bx >= t3.blk0) ? t3 : (bx >= t2.blk0) ? t2 : (bx >= t1.blk0) ? t1 : t0;
    const int rel = bx - jb.blk0;
    const int n0 = (rel % jb.nbx) * 32, k0 = (rel / jb.nbx) * 32;
    const int tid = threadIdx.x;
    {
        const int lr = tid >> 3, lc = (tid & 7) * 4;
        float4 v = *(const float4*)(jb.B + (size_t)(k0 + lr) * jb.Nd + n0 + lc);
        t[lr][lc] = v.x; t[lr][lc + 1] = v.y; t[lr][lc + 2] = v.z; t[lr][lc + 3] = v.w;
    }
    __syncthreads();
    const int p = tid & 15, nl0 = tid >> 4;
    #pragma unroll
    for (int u = 0; u < 2; u++) {
        const int n = nl0 + u * 16;
        uint32_t h, l;
        split2_bf(t[2 * p][n], t[2 * p + 1][n], h, l);
        jb.Th[(size_t)(n0 + n) * K2DIM + (k0 >> 1) + p] = h;
        jb.Tl[(size_t)(n0 + n) * K2DIM + (k0 >> 1) + p] = l;
    }
}

// ---------------- block reduce ----------------------------------------------
static __device__ __forceinline__ float blockReduceSum(float v, float* sh) {
    #pragma unroll
    for (int o = 16; o; o >>= 1) v += __shfl_xor_sync(0xffffffffu, v, o);
    int w = threadIdx.x >> 5;
    if ((threadIdx.x & 31) == 0) sh[w] = v;
    __syncthreads();
    if (threadIdx.x < 32) {
        v = (threadIdx.x < 8) ? sh[threadIdx.x] : 0.f;
        #pragma unroll
        for (int o = 4; o; o >>= 1) v += __shfl_xor_sync(0xffffffffu, v, o);
        if (threadIdx.x == 0) sh[0] = v;
    }
    __syncthreads();
    float r = sh[0];
    __syncthreads();
    return r;
}

// ---------------- fused prep: ln_split (rows<4096) + mlp0_split -------------
__global__ void prep_fused(const float* __restrict__ x, const float* __restrict__ gn,
                           const float* __restrict__ w0, const float* __restrict__ b0,
                           const float* __restrict__ g0) {
    __shared__ float sh[32];
    const int tid = threadIdx.x;
    if (blockIdx.x < ROWS) {
        const int row = blockIdx.x;
        float4 v = *(const float4*)(x + (size_t)row * DIM + tid * 4);
        float s = v.x + v.y + v.z + v.w;
        s = blockReduceSum(s, sh);
        float mean = s * (1.f / DIM);
        float d0 = v.x - mean, d1 = v.y - mean, d2 = v.z - mean, d3 = v.w - mean;
        float qv = d0 * d0 + d1 * d1 + d2 * d2 + d3 * d3;
        qv = blockReduceSum(qv, sh);
        float rstd = rsqrtf(qv * (1.f / DIM) + 1e-5f);
        float4 gg = *(const float4*)(gn + tid * 4);
        float o0 = d0 * rstd * gg.x, o1 = d1 * rstd * gg.y;
        float o2 = d2 * rstd * gg.z, o3 = d3 * rstd * gg.w;
        uint32_t h0, l0, h1, l1;
        split2_bf(o0, o1, h0, l0);
        split2_bf(o2, o3, h1, l1);
        ((uint2*)g_xnh)[(size_t)row * 256 + tid] = make_uint2(h0, h1);
        ((uint2*)g_xnl)[(size_t)row * 256 + tid] = make_uint2(l0, l1);
    } else {
        const int d = blockIdx.x - ROWS;
        const float pos = (float)d;
        const int c = tid * 4;
        float4 w4 = *(const float4*)(w0 + c);
        float4 b4 = *(const float4*)(b0 + c);
        float v0 = pos * w4.x + b4.x, v1 = pos * w4.y + b4.y;
        float v2 = pos * w4.z + b4.z, v3 = pos * w4.w + b4.w;
        float s = v0 + v1 + v2 + v3;
        s = blockReduceSum(s, sh);
        float mean = s * (1.f / DIM);
        float d0 = v0 - mean, d1 = v1 - mean, d2 = v2 - mean, d3 = v3 - mean;
        float qv = d0 * d0 + d1 * d1 + d2 * d2 + d3 * d3;
        qv = blockReduceSum(qv, sh);
        float rstd = rsqrtf(qv * (1.f / DIM) + 1e-5f);
        float4 g4 = *(const float4*)(g0 + c);
        float o0 = d0 * rstd * g4.x; o0 = o0 / (1.f + __expf(-o0));
        float o1 = d1 * rstd * g4.y; o1 = o1 / (1.f + __expf(-o1));
        float o2 = d2 * rstd * g4.z; o2 = o2 / (1.f + __expf(-o2));
        float o3 = d3 * rstd * g4.w; o3 = o3 / (1.f + __expf(-o3));
        uint32_t h0, l0, h1, l1;
        split2_bf(o0, o1, h0, l0);
        split2_bf(o2, o3, h1, l1);
        ((uint2*)g_h0h)[(size_t)d * 256 + tid] = make_uint2(h0, h1);
        ((uint2*)g_h0l)[(size_t)d * 256 + tid] = make_uint2(l0, l1);
    }
}

// ---------------- layernorm rows (fp32 out; optional bias + silu) -----------
__global__ void ln_rows(const float* __restrict__ in, const float* __restrict__ bias,
                        const float* __restrict__ g, float* __restrict__ out, int dosilu) {
    __shared__ float sh[32];
    const int row = blockIdx.x, tid = threadIdx.x;
    float v[4];
    #pragma unroll
    for (int u = 0; u < 4; u++) {
        int c = tid + u * 256;
        v[u] = in[(size_t)row * DIM + c] + (bias ? bias[c] : 0.f);
    }
    float s = v[0] + v[1] + v[2] + v[3];
    s = blockReduceSum(s, sh);
    float mean = s * (1.f / DIM);
    float qv = 0.f;
    #pragma unroll
    for (int u = 0; u < 4; u++) { float d = v[u] - mean; qv += d * d; }
    qv = blockReduceSum(qv, sh);
    float rstd = rsqrtf(qv * (1.f / DIM) + 1e-5f);
    #pragma unroll
    for (int u = 0; u < 4; u++) {
        int c = tid + u * 256;
        float o = (v[u] - mean) * rstd * g[c];
        if (dosilu) o = o / (1.f + __expf(-o));
        out[(size_t)row * DIM + c] = o;
    }
}

// ---------------- btabT[16][2048] = h1 @ w2 + b2 ----------------------------
__global__ void w2_kernel(const float* __restrict__ w2, const float* __restrict__ b2) {
    __shared__ float sh[DIM];
    const int d = blockIdx.x, tid = threadIdx.x;
    #pragma unroll
    for (int u = 0; u < 4; u++) sh[tid + u * 256] = g_h0[(size_t)d * DIM + tid + u * 256];
    __syncthreads();
    const int gi = tid >> 4, l16 = tid & 15;
    float s = 0.f;
    for (int kk = l16; kk < DIM; kk += 16) s += sh[kk] * w2[kk * HEADS + gi];
    #pragma unroll
    for (int o = 8; o; o >>= 1) s += __shfl_xor_sync(0xffffffffu, s, o);
    if (l16 == 0) g_btab[gi * N_TOK + d] = s + b2[gi];
}

// ---------------- fused norms: qnorm + kvnorm + nullprep --------------------
#define QN_BLOCKS (ROWS * HEADS / 8)   // 8192
#define KV_BLOCKS (ROWS / 8)           // 512

__global__ void norm_fused(const float* __restrict__ qs, const float* __restrict__ ks,
                           const float* __restrict__ nkv) {
    const int bx = blockIdx.x, tid = threadIdx.x;
    const int lane = tid & 31;
    if (bx < QN_BLOCKS) {
        const int gw = (bx * 256 + tid) >> 5;
        const int row = gw >> 4, h = gw & 15;
        float* p = g_q + (size_t)row * DIM + h * DHEAD;
        const int d0 = lane * 2;
        float a = p[d0], b = p[d0 + 1];
        float ss = a * a + b * b;
        #pragma unroll
        for (int o = 16; o; o >>= 1) ss += __shfl_xor_sync(0xffffffffu, ss, o);
        float inv = 1.f / fmaxf(sqrtf(ss), 1e-12f);
        p[d0]     = a * inv * qs[d0];
        p[d0 + 1] = b * inv * qs[d0 + 1];
    } else if (bx < QN_BLOCKS + KV_BLOCKS) {
        const int row = ((bx - QN_BLOCKS) * 256 + tid) >> 5;
        const float* kvp = g_kv + (size_t)row * 128;
        const int d0 = lane * 2;
        float a = kvp[d0], b = kvp[d0 + 1];
        float ss = a * a + b * b;
        #pragma unroll
        for (int o = 16; o; o >>= 1) ss += __shfl_xor_sync(0xffffffffu, ss, o);
        float inv = 1.f / fmaxf(sqrtf(ss), 1e-12f);
        g_k[(size_t)row * DHEAD + d0]     = a * inv * ks[d0];
        g_k[(size_t)row * DHEAD + d0 + 1] = b * inv * ks[d0 + 1];
        g_v[(size_t)row * DHEAD + d0]     = kvp[64 + d0];
        g_v[(size_t)row * DHEAD + d0 + 1] = kvp[64 + d0 + 1];
    } else if (tid < 32) {
        const int d0 = lane * 2;
        float a = nkv[d0], b = nkv[d0 + 1];
        float ss = a * a + b * b;
        #pragma unroll
        for (int o = 16; o; o >>= 1) ss += __shfl_xor_sync(0xffffffffu, ss, o);
        float inv = 1.f / fmaxf(sqrtf(ss), 1e-12f);
        g_knull[d0]     = a * inv * ks[d0];
        g_knull[d0 + 1] = b * inv * ks[d0 + 1];
        g_vnull[d0]     = nkv[64 + d0];
        g_vnull[d0 + 1] = nkv[64 + d0 + 1];
    }
}

// ---------------- causal MQA flash attention via bf16-split2 mma.sync -------
// 128 Q-rows x 64 KV tile. 8 warps; warp wid owns Q rows [16*wid, 16*wid+16).
// Smem operands stored as bf16 pairs with row stride 36 u32 (conflict-free
// fragment loads; identical addressing to gemm_fat). P stays in registers:
// the m16n8k16 C layout IS the A-fragment layout for PV.
#define PROW 36
#define ATT_SMEM_U32 (128 * PROW * 2 + 64 * PROW * 2 + 64 * PROW * 2 + 320)
#define ATT_SMEM_BYTES (ATT_SMEM_U32 * 4)   // 75008

__global__ __launch_bounds__(256, 1) void attn_kernel(
        const float* __restrict__ q, const float* __restrict__ kbuf,
        const float* __restrict__ vbuf, const float* __restrict__ knull,
        const float* __restrict__ vnull, const float* __restrict__ nab,
        const float* __restrict__ btab) {
    extern __shared__ uint32_t su[];
    uint32_t* Qh = su;                       // [128][PROW]
    uint32_t* Ql = su + 128 * PROW;          // 4608
    uint32_t* Kh = su + 2 * 128 * PROW;      // 9216, [64][PROW]
    uint32_t* Kl = Kh + 64 * PROW;
    uint32_t* Vh = Kl + 64 * PROW;           // [64][PROW], row=d, pairs over jj
    uint32_t* Vl = Vh + 64 * PROW;
    float* bsl = (float*)(Vl + 64 * PROW);   // 192
    float* kns = bsl + 192;                  // 64
    float* vns = kns + 64;                   // 64

    const int tid = threadIdx.x, wid = tid >> 5, lane = tid & 31;
    const int g = lane >> 2, tig = lane & 3;
    const int i0 = (gridDim.x - 1 - blockIdx.x) * 128;
    const int h  = blockIdx.y;
    const int b  = blockIdx.z;

    {   // load + split Q tile: 2 threads per row, 32 elems each = 16 pairs
        const int row = tid >> 1, half = tid & 1;
        const float* src = q + (size_t)(b * N_TOK + i0 + row) * DIM + h * DHEAD + half * 32;
        #pragma unroll
        for (int u = 0; u < 8; u++) {
            float4 v = *(const float4*)(src + u * 4);
            uint32_t h0, l0, h1, l1;
            split2_bf(v.x, v.y, h0, l0);
            split2_bf(v.z, v.w, h1, l1);
            const int pb = row * PROW + half * 16 + u * 2;
            Qh[pb] = h0; Qh[pb + 1] = h1;
            Ql[pb] = l0; Ql[pb + 1] = l1;
        }
    }
    if (tid < 64) { kns[tid] = knull[tid]; vns[tid] = vnull[tid]; }
    __syncthreads();

    // init m/l (null key) and O accumulator (null value)
    const int rl = 16 * wid + g;             // local Q row (second row = rl+8)
    float m2[2], l2[2], c_o[8][4];
    {
        const float nb = nab[h];
        #pragma unroll
        for (int rr = 0; rr < 2; rr++) {
            const int qb = (rl + rr * 8) * PROW;
            float p = 0.f;
            #pragma unroll
            for (int pp = 0; pp < 8; pp++) {
                const int pi = tig * 8 + pp;
                float v0 = bfu(Qh[qb + pi], 0) + bfu(Ql[qb + pi], 0);
                float v1 = bfu(Qh[qb + pi], 1) + bfu(Ql[qb + pi], 1);
                p += v0 * kns[2 * pi] + v1 * kns[2 * pi + 1];
            }
            p += __shfl_xor_sync(0xffffffffu, p, 1);
            p += __shfl_xor_sync(0xffffffffu, p, 2);
            m2[rr] = p * 8.f + nb;
            l2[rr] = 1.f;
        }
        #pragma unroll
        for (int nd = 0; nd < 8; nd++) {
            const int d0 = 8 * nd + 2 * tig;
            c_o[nd][0] = vns[d0];     c_o[nd][1] = vns[d0 + 1];
            c_o[nd][2] = vns[d0];     c_o[nd][3] = vns[d0 + 1];
        }
    }

    const int ntiles = i0 / 64 + 2;
    for (int jt = 0; jt < ntiles; jt++) {
        const int j0 = jt * 64;
        {   // load + split K (row-major over dd) and V-transposed (pairs over jj)
            #pragma unroll
            for (int u = 0; u < 2; u++) {
                const int row = (tid >> 3) + u * 32;      // K row (jj)
                const int pp = (tid & 7) * 4;             // pair base (dd)
                const float* ks = kbuf + (size_t)(b * N_TOK + j0 + row) * DHEAD + pp * 2;
                float4 a0 = *(const float4*)(ks);
                float4 a1 = *(const float4*)(ks + 4);
                uint32_t h0, l0;
                split2_bf(a0.x, a0.y, h0, l0); Kh[row * PROW + pp]     = h0; Kl[row * PROW + pp]     = l0;
                split2_bf(a0.z, a0.w, h0, l0); Kh[row * PROW + pp + 1] = h0; Kl[row * PROW + pp + 1] = l0;
                split2_bf(a1.x, a1.y, h0, l0); Kh[row * PROW + pp + 2] = h0; Kl[row * PROW + pp + 2] = l0;
                split2_bf(a1.z, a1.w, h0, l0); Kh[row * PROW + pp + 3] = h0; Kl[row * PROW + pp + 3] = l0;
            }
            {   // V: thread -> jj pair (tid&31), d segment (tid>>5)*8
                const int jjp = tid & 31, dseg = (tid >> 5) * 8;
                const float* v0 = vbuf + (size_t)(b * N_TOK + j0 + 2 * jjp) * DHEAD + dseg;
                const float* v1 = v0 + DHEAD;
                float4 a0 = *(const float4*)(v0);
                float4 a1 = *(const float4*)(v0 + 4);
                float4 b0 = *(const float4*)(v1);
                float4 b1 = *(const float4*)(v1 + 4);
                uint32_t hh, ll;
                split2_bf(a0.x, b0.x, hh, ll); Vh[(dseg + 0) * PROW + jjp] = hh; Vl[(dseg + 0) * PROW + jjp] = ll;
                split2_bf(a0.y, b0.y, hh, ll); Vh[(dseg + 1) * PROW + jjp] = hh; Vl[(dseg + 1) * PROW + jjp] = ll;
                split2_bf(a0.z, b0.z, hh, ll); Vh[(dseg + 2) * PROW + jjp] = hh; Vl[(dseg + 2) * PROW + jjp] = ll;
                split2_bf(a0.w, b0.w, hh, ll); Vh[(dseg + 3) * PROW + jjp] = hh; Vl[(dseg + 3) * PROW + jjp] = ll;
                split2_bf(a1.x, b1.x, hh, ll); Vh[(dseg + 4) * PROW + jjp] = hh; Vl[(dseg + 4) * PROW + jjp] = ll;
                split2_bf(a1.y, b1.y, hh, ll); Vh[(dseg + 5) * PROW + jjp] = hh; Vl[(dseg + 5) * PROW + jjp] = ll;
                split2_bf(a1.z, b1.z, hh, ll); Vh[(dseg + 6) * PROW + jjp] = hh; Vl[(dseg + 6) * PROW + jjp] = ll;
                split2_bf(a1.w, b1.w, hh, ll); Vh[(dseg + 7) * PROW + jjp] = hh; Vl[(dseg + 7) * PROW + jjp] = ll;
            }
        }
        if (tid < 191) {
            int dg = i0 - j0 + tid - 63;
            bsl[tid] = (dg >= 0 && dg < N_TOK) ? btab[h * N_TOK + dg] : 0.f;
        }
        __syncthreads();

        // S = Q @ K^T via split-2 bf16 MMA
        float c_s[8][4] = {};
        const int qb0 = rl * PROW;
        #pragma unroll
        for (int kk = 0; kk < 4; kk++) {
            uint32_t ah[4], al[4];
            ah[0] = Qh[qb0 + 8 * kk + tig];               ah[1] = Qh[qb0 + 8 * PROW + 8 * kk + tig];
            ah[2] = Qh[qb0 + 8 * kk + tig + 4];           ah[3] = Qh[qb0 + 8 * PROW + 8 * kk + tig + 4];
            al[0] = Ql[qb0 + 8 * kk + tig];               al[1] = Ql[qb0 + 8 * PROW + 8 * kk + tig];
            al[2] = Ql[qb0 + 8 * kk + tig + 4];           al[3] = Ql[qb0 + 8 * PROW + 8 * kk + tig + 4];
            #pragma unroll
            for (int nj = 0; nj < 8; nj++) {
                const int kb = (8 * nj + g) * PROW + 8 * kk + tig;
                uint32_t bh2[2] = { Kh[kb], Kh[kb + 4] };
                uint32_t bl2[2] = { Kl[kb], Kl[kb + 4] };
                mma_bf16(c_s[nj], ah, bh2);
                mma_bf16(c_s[nj], al, bh2);
                mma_bf16(c_s[nj], ah, bl2);
            }
        }

        // bias + causal mask
        const bool needmask = (j0 >= i0);
        #pragma unroll
        for (int nj = 0; nj < 8; nj++) {
            const int cl = 8 * nj + 2 * tig;
            const int bidx = rl - cl + 63;
            c_s[nj][0] = c_s[nj][0] * 8.f + bsl[bidx];
            c_s[nj][1] = c_s[nj][1] * 8.f + bsl[bidx - 1];
            c_s[nj][2] = c_s[nj][2] * 8.f + bsl[bidx + 8];
            c_s[nj][3] = c_s[nj][3] * 8.f + bsl[bidx + 7];
            if (needmask) {
                const int col = j0 + cl;
                if (col     > i0 + rl)     c_s[nj][0] = -1e30f;
                if (col + 1 > i0 + rl)     c_s[nj][1] = -1e30f;
                if (col     > i0 + rl + 8) c_s[nj][2] = -1e30f;
                if (col + 1 > i0 + rl + 8) c_s[nj][3] = -1e30f;
            }
        }

        // online softmax (quad reductions)
        float fac[2];
        #pragma unroll
        for (int rr = 0; rr < 2; rr++) {
            float mt = -1e30f;
            #pragma unroll
            for (int nj = 0; nj < 8; nj++)
                mt = fmaxf(mt, fmaxf(c_s[nj][2 * rr], c_s[nj][2 * rr + 1]));
            mt = fmaxf(mt, __shfl_xor_sync(0xffffffffu, mt, 1));
            mt = fmaxf(mt, __shfl_xor_sync(0xffffffffu, mt, 2));
            float nm = fmaxf(m2[rr], mt);
            fac[rr] = __expf(m2[rr] - nm);
            m2[rr] = nm;
            float lt = 0.f;
            #pragma unroll
            for (int nj = 0; nj < 8; nj++) {
                float p0 = __expf(c_s[nj][2 * rr] - nm);
                float p1 = __expf(c_s[nj][2 * rr + 1] - nm);
                c_s[nj][2 * rr] = p0; c_s[nj][2 * rr + 1] = p1;
                lt += p0 + p1;
            }
            lt += __shfl_xor_sync(0xffffffffu, lt, 1);
            lt += __shfl_xor_sync(0xffffffffu, lt, 2);
            l2[rr] = l2[rr] * fac[rr] + lt;
        }
        #pragma unroll
        for (int nd = 0; nd < 8; nd++) {
            c_o[nd][0] *= fac[0]; c_o[nd][1] *= fac[0];
            c_o[nd][2] *= fac[1]; c_o[nd][3] *= fac[1];
        }

        // O += P @ V: P a-frags come straight from c_s registers
        #pragma unroll
        for (int kk = 0; kk < 4; kk++) {
            uint32_t pha[4], pla[4];
            split2_bf(c_s[2 * kk][0],     c_s[2 * kk][1],     pha[0], pla[0]);
            split2_bf(c_s[2 * kk][2],     c_s[2 * kk][3],     pha[1], pla[1]);
            split2_bf(c_s[2 * kk + 1][0], c_s[2 * kk + 1][1], pha[2], pla[2]);
            split2_bf(c_s[2 * kk + 1][2], c_s[2 * kk + 1][3], pha[3], pla[3]);
            #pragma unroll
            for (int nd = 0; nd < 8; nd++) {
                const int kb = (8 * nd + g) * PROW + 8 * kk + tig;
                uint32_t vh2[2] = { Vh[kb], Vh[kb + 4] };
                uint32_t vl2[2] = { Vl[kb], Vl[kb + 4] };
                mma_bf16(c_o[nd], pha, vh2);
                mma_bf16(c_o[nd], pla, vh2);
                mma_bf16(c_o[nd], pha, vl2);
            }
        }
        __syncthreads();
    }

    // epilogue: normalize, split to bf16 hi/lo, direct pair store
    {
        const float inv0 = 1.f / l2[0], inv1 = 1.f / l2[1];
        const size_t r0b = (size_t)(b * N_TOK + i0 + rl) * K2DIM;
        const size_t r1b = (size_t)(b * N_TOK + i0 + rl + 8) * K2DIM;
        #pragma unroll
        for (int nd = 0; nd < 8; nd++) {
            const int pidx = h * 32 + 4 * nd + tig;
            uint32_t hh, ll;
            split2_bf(c_o[nd][0] * inv0, c_o[nd][1] * inv0, hh, ll);
            g_aoh[r0b + pidx] = hh; g_aol[r0b + pidx] = ll;
            split2_bf(c_o[nd][2] * inv1, c_o[nd][3] * inv1, hh, ll);
            g_aoh[r1b + pidx] = hh; g_aol[r1b + pidx] = ll;
        }
    }
}

// ---------------- launch -----------------------------------------------------
extern "C" void kernel_launch(void* const* d_in, const int* in_sizes, int n_in,
                              void* d_out, int out_size) {
    const float* x       = (const float*)d_in[0];
    const float* gn      = (const float*)d_in[2];
    const float* Wq      = (const float*)d_in[3];
    const float* Wkv     = (const float*)d_in[4];
    const float* q_scale = (const float*)d_in[5];
    const float* k_scale = (const float*)d_in[6];
    const float* null_kv = (const float*)d_in[7];
    const float* nab     = (const float*)d_in[8];
    const float* w0      = (const float*)d_in[9];
    const float* b0      = (const float*)d_in[10];
    const float* g0      = (const float*)d_in[11];
    const float* w1      = (const float*)d_in[12];
    const float* b1      = (const float*)d_in[13];
    const float* g1      = (const float*)d_in[14];
    const float* w2      = (const float*)d_in[15];
    const float* b2      = (const float*)d_in[16];
    const float* Wout    = (const float*)d_in[17];
    const float* gout    = (const float*)d_in[18];
    float* out = (float*)d_out;

    float *pq, *pkv, *pk, *pv, *pknull, *pvnull, *ph0, *pt1, *pbtab, *py;
    uint32_t *pxnh, *pxnl, *ph0h, *ph0l, *paoh, *paol;
    uint32_t *pWqTh, *pWqTl, *pWkvTh, *pWkvTl, *pw1Th, *pw1Tl, *pWoutTh, *pWoutTl;
    cudaGetSymbolAddress((void**)&pq,      g_q);
    cudaGetSymbolAddress((void**)&pkv,     g_kv);
    cudaGetSymbolAddress((void**)&pk,      g_k);
    cudaGetSymbolAddress((void**)&pv,      g_v);
    cudaGetSymbolAddress((void**)&pknull,  g_knull);
    cudaGetSymbolAddress((void**)&pvnull,  g_vnull);
    cudaGetSymbolAddress((void**)&ph0,     g_h0);
    cudaGetSymbolAddress((void**)&pt1,     g_t1);
    cudaGetSymbolAddress((void**)&pbtab,   g_btab);
    cudaGetSymbolAddress((void**)&py,      g_y);
    cudaGetSymbolAddress((void**)&pxnh,    g_xnh);
    cudaGetSymbolAddress((void**)&pxnl,    g_xnl);
    cudaGetSymbolAddress((void**)&ph0h,    g_h0h);
    cudaGetSymbolAddress((void**)&ph0l,    g_h0l);
    cudaGetSymbolAddress((void**)&paoh,    g_aoh);
    cudaGetSymbolAddress((void**)&paol,    g_aol);
    cudaGetSymbolAddress((void**)&pWqTh,   g_WqTh);
    cudaGetSymbolAddress((void**)&pWqTl,   g_WqTl);
    cudaGetSymbolAddress((void**)&pWkvTh,  g_WkvTh);
    cudaGetSymbolAddress((void**)&pWkvTl,  g_WkvTl);
    cudaGetSymbolAddress((void**)&pw1Th,   g_w1Th);
    cudaGetSymbolAddress((void**)&pw1Tl,   g_w1Tl);
    cudaGetSymbolAddress((void**)&pWoutTh, g_WoutTh);
    cudaGetSymbolAddress((void**)&pWoutTl, g_WoutTl);

    cudaFuncSetAttribute(attn_kernel, cudaFuncAttributeMaxDynamicSharedMemorySize, ATT_SMEM_BYTES);
    cudaFuncSetAttribute(gemm_fat, cudaFuncAttributeMaxDynamicSharedMemorySize, GEMM_SMEM_BYTES);

    // 0. transpose + split all 4 weight matrices (one fat launch)
    {
        TJob t0 = { Wq,   pWqTh,   pWqTl,   DIM, 32, 0 };
        TJob t1j = { Wkv,  pWkvTh,  pWkvTl,  2 * DHEAD, 4, 1024 };
        TJob t2 = { w1,   pw1Th,   pw1Tl,   DIM, 32, 1152 };
        TJob t3 = { Wout, pWoutTh, pWoutTl, DIM, 32, 2176 };
        transpose_split4<<<3200, 256>>>(t0, t1j, t2, t3);
    }
    // 1. fused ln_split(x) + mlp0_split
    prep_fused<<<ROWS + N_TOK, 256>>>(x, gn, w0, b0, g0);
    // 2. fat GEMM: q = xn@Wq | t1 = h0@w1 | kv = xn@Wkv (one launch, 416 blocks)
    {
        GJob j0 = { pxnh, pxnl, pWqTh,  pWqTl,  pq,  DIM, 8, 0 };
        GJob j1 = { ph0h, ph0l, pw1Th,  pw1Tl,  pt1, DIM, 8, 256 };
        GJob j2 = { pxnh, pxnl, pWkvTh, pWkvTl, pkv, 2 * DHEAD, 1, 384 };
        gemm_fat<<<416, 256, GEMM_SMEM_BYTES>>>(j0, j1, j2);
    }
    // 3. fused qnorm + kvnorm + nullprep
    norm_fused<<<QN_BLOCKS + KV_BLOCKS + 1, 256>>>(q_scale, k_scale, null_kv);
    // 4. rel-pos bias: ln(t1)+silu -> h0 ; btab = h0@w2
    ln_rows<<<N_TOK, 256>>>(pt1, b1, g1, ph0, 1);
    w2_kernel<<<N_TOK, 256>>>(w2, b2);
    // 5. flash attention via tensor cores; epilogue writes split bf16 aout
    attn_kernel<<<dim3(N_TOK / 128, HEADS, BATCH), 256, ATT_SMEM_BYTES>>>(
        pq, pk, pv, pknull, pvnull, nab, pbtab);
    // 6. y = aout @ Wout ; out = ln(y) * g_out
    {
        GJob j0 = { paoh, paol, pWoutTh, pWoutTl, py, DIM, 8, 0 };
        GJob jx = { paoh, paol, pWoutTh, pWoutTl, py, DIM, 8, 1 << 30 };
        gemm_fat<<<256, 256, GEMM_SMEM_BYTES>>>(j0, jx, jx);
    }
    ln_rows<<<ROWS, 256>>>(py, nullptr, gout, out, 0);
}